// round 5
// baseline (speedup 1.0000x reference)
#include <cuda_runtime.h>
#include <math.h>
#include <stdint.h>

#define NN   300000
#define NE   299999
#define NA   150000
#define DD   64
#define HH   128

// ---------------- scratch ----------------
__device__ float g_h   [(size_t)NN * HH];
__device__ float g_xl  [(size_t)NN * HH];
__device__ float g_xr  [(size_t)NN * HH];
__device__ float g_acc [(size_t)NN * HH];
__device__ float g_den [NN];
__device__ float g_ctx [HH];
__device__ float g_cadd[HH];

// ---------------- tf32 helpers ----------------
__device__ __forceinline__ uint32_t f2tf32(float f)
{
    uint32_t u;
    asm("cvt.rna.tf32.f32 %0, %1;" : "=r"(u) : "f"(f));
    return u;
}
__device__ __forceinline__ float tf32f(float f) { return __uint_as_float(f2tf32(f)); }

__device__ __forceinline__ void mma_tf32(float* d, const uint32_t* a, const uint32_t* b)
{
    asm volatile(
        "mma.sync.aligned.m16n8k8.row.col.f32.tf32.tf32.f32 "
        "{%0,%1,%2,%3},{%4,%5,%6,%7},{%8,%9},{%0,%1,%2,%3};"
        : "+f"(d[0]), "+f"(d[1]), "+f"(d[2]), "+f"(d[3])
        : "r"(a[0]), "r"(a[1]), "r"(a[2]), "r"(a[3]), "r"(b[0]), "r"(b[1]));
}

#define WNP 136          // W smem pitch [k][n]
#define AP128 164        // A pitch: 16 kchunks * 10 + 4
#define AP64  84         // A pitch: 8 kchunks * 10 + 4
#define AP256 324        // A pitch: 32 kchunks * 10 + 4

// k-permutation within an 8-chunk: order [0,4,1,5,2,6,3,7]
// p(kk) = 2*(kk&3) + (kk>>2); pair (tig, tig+4) sits at (2*tig, 2*tig+1)

// fragment mainloop: warp tile (MF*16) x (NF*8), A in paired layout, W in [k][n]
template <int MF, int NF, int NK>
__device__ __forceinline__ void mma_loop(
    const float* As, int apitch, int aoff, const float* Ws,
    int wrow, int wcol, int gid, int tig, float acc[MF][NF][4])
{
#pragma unroll
    for (int ks = 0; ks < NK; ++ks) {
        const int k0 = ks * 8;
        uint32_t a[MF][4], b[NF][2];
#pragma unroll
        for (int mf = 0; mf < MF; ++mf) {
            const float* ap = As + (wrow + mf * 16 + gid) * apitch + aoff + ks * 10 + 2 * tig;
            float2 lo = *(const float2*)ap;
            float2 hi = *(const float2*)(ap + 8 * apitch);
            a[mf][0] = __float_as_uint(lo.x);
            a[mf][1] = __float_as_uint(hi.x);
            a[mf][2] = __float_as_uint(lo.y);
            a[mf][3] = __float_as_uint(hi.y);
        }
#pragma unroll
        for (int nf = 0; nf < NF; ++nf) {
            const int c = wcol + nf * 8 + gid;
            b[nf][0] = __float_as_uint(Ws[(k0 + tig) * WNP + c]);
            b[nf][1] = __float_as_uint(Ws[(k0 + tig + 4) * WNP + c]);
        }
#pragma unroll
        for (int mf = 0; mf < MF; ++mf)
#pragma unroll
            for (int nf = 0; nf < NF; ++nf)
                mma_tf32(acc[mf][nf], a[mf], b[nf]);
    }
}

// stage W [K x 128] row-major -> Ws [k][n] pitch WNP, tf32 (128-thread block)
template <int K>
__device__ __forceinline__ void stage_w(const float* __restrict__ W, float* Ws, int tid)
{
    for (int i = tid; i < K * 32; i += 128) {
        int k = i >> 5, c4 = i & 31;
        float4 v = ((const float4*)W)[i];
        float* wp = Ws + k * WNP + c4 * 4;
        wp[0] = tf32f(v.x); wp[1] = tf32f(v.y); wp[2] = tf32f(v.z); wp[3] = tf32f(v.w);
    }
}

// write a float4 of 4 consecutive k (k = 4*c4..4*c4+3) into paired layout
__device__ __forceinline__ void store_paired4(float* base, int c4, float4 v)
{
    // ks = c4>>1, odd = c4&1 ; positions 2j + odd
    float* p = base + (c4 >> 1) * 10 + (c4 & 1);
    p[0] = tf32f(v.x); p[2] = tf32f(v.y); p[4] = tf32f(v.z); p[6] = tf32f(v.w);
}

// ---------- fused embed + dual transform ----------
__global__ __launch_bounds__(128, 1) void embed_dual(
    const float* __restrict__ x,
    const float* __restrict__ We, const float* __restrict__ be,
    const float* __restrict__ Wl, const float* __restrict__ bl,
    const float* __restrict__ Wr, const float* __restrict__ br,
    float* __restrict__ Hout, float* __restrict__ Cl, float* __restrict__ Cr, int M)
{
    extern __shared__ float sh[];
    float* As  = sh;                       // 128 x AP128 (phase A uses AP64)
    float* Ws0 = sh + 128 * AP128;
    float* Ws1 = Ws0 + 128 * WNP;
    const int tid = threadIdx.x;
    const int row0 = blockIdx.x * 128;

    // phase A: stage x (K=64, paired, pitch AP64) and W_embed
    stage_w<64>(We, Ws0, tid);
    for (int i = tid; i < 128 * 16; i += 128) {
        int r = i >> 4, c4 = i & 15;
        int gr = row0 + r;
        float4 v = make_float4(0.f, 0.f, 0.f, 0.f);
        if (gr < M) v = ((const float4*)(x + (size_t)gr * 64))[c4];
        store_paired4(As + r * AP64, c4, v);
    }
    __syncthreads();

    const int wid = tid >> 5, lane = tid & 31;
    const int wm = wid & 1, wn = wid >> 1;      // warp tile 64x64
    const int wrow = wm * 64, wcol = wn * 64;
    const int gid = lane >> 2, tig = lane & 3;

    float acc[4][8][4];
#pragma unroll
    for (int mf = 0; mf < 4; ++mf)
#pragma unroll
        for (int nf = 0; nf < 8; ++nf)
#pragma unroll
            for (int j = 0; j < 4; ++j) acc[mf][nf][j] = 0.f;

    mma_loop<4, 8, 8>(As, AP64, 0, Ws0, wrow, wcol, gid, tig, acc);
    __syncthreads();   // phase-A reads complete before As/Ws0 overwrite

    // epilogue h: write gmem + restage paired into As (pitch AP128)
#pragma unroll
    for (int nf = 0; nf < 8; ++nf) {
        const int c = wcol + nf * 8 + tig * 2;
        const int ks = c >> 3, kk = c & 7;
        const int p0 = ((kk & 3) << 1) | (kk >> 2);
        const int p1 = (((kk + 1) & 3) << 1) | ((kk + 1) >> 2);
        const float b0 = be[c], b1 = be[c + 1];
#pragma unroll
        for (int mf = 0; mf < 4; ++mf)
#pragma unroll
            for (int h = 0; h < 2; ++h) {
                const int rl = wrow + mf * 16 + h * 8 + gid;
                const float v0 = acc[mf][nf][2 * h] + b0;
                const float v1 = acc[mf][nf][2 * h + 1] + b1;
                const int gr = row0 + rl;
                if (gr < M)
                    *(float2*)(Hout + (size_t)gr * 128 + c) = make_float2(v0, v1);
                float* ap = As + rl * AP128 + ks * 10;
                ap[p0] = tf32f(v0);
                ap[p1] = tf32f(v1);
            }
    }
    stage_w<128>(Wl, Ws0, tid);
    stage_w<128>(Wr, Ws1, tid);
    __syncthreads();

#pragma unroll
    for (int ph = 0; ph < 2; ++ph) {
        const float* Ws   = ph ? Ws1 : Ws0;
        const float* bias = ph ? br  : bl;
        float* C          = ph ? Cr  : Cl;
#pragma unroll
        for (int mf = 0; mf < 4; ++mf)
#pragma unroll
            for (int nf = 0; nf < 8; ++nf)
#pragma unroll
                for (int j = 0; j < 4; ++j) acc[mf][nf][j] = 0.f;
        mma_loop<4, 8, 16>(As, AP128, 0, Ws, wrow, wcol, gid, tig, acc);
#pragma unroll
        for (int nf = 0; nf < 8; ++nf) {
            const int c = wcol + nf * 8 + tig * 2;
            const float b0 = bias[c], b1 = bias[c + 1];
#pragma unroll
            for (int mf = 0; mf < 4; ++mf)
#pragma unroll
                for (int h = 0; h < 2; ++h) {
                    const int r = row0 + wrow + mf * 16 + h * 8 + gid;
                    if (r < M)
                        *(float2*)(C + (size_t)r * 128 + c) =
                            make_float2(acc[mf][nf][2 * h] + b0, acc[mf][nf][2 * h + 1] + b1);
                }
        }
    }
}

// ---------- dual transform with fused update ----------
__global__ __launch_bounds__(128, 1) void dual_upd(
    float* __restrict__ H, const float* __restrict__ Acc, const float* __restrict__ Den,
    const float* __restrict__ ubias,
    const float* __restrict__ Wl, const float* __restrict__ bl,
    const float* __restrict__ Wr, const float* __restrict__ br,
    float* __restrict__ Cl, float* __restrict__ Cr, int M)
{
    extern __shared__ float sh[];
    float* As  = sh;
    float* Ws0 = sh + 128 * AP128;
    float* Ws1 = Ws0 + 128 * WNP;
    const int tid = threadIdx.x;
    const int row0 = blockIdx.x * 128;

    stage_w<128>(Wl, Ws0, tid);
    stage_w<128>(Wr, Ws1, tid);

    for (int i = tid; i < 128 * 32; i += 128) {
        int r = i >> 5, c4 = i & 31;
        int gr = row0 + r;
        float4 hv = make_float4(0.f, 0.f, 0.f, 0.f);
        if (gr < M) {
            float inv = 1.f / (Den[gr] + 1e-16f);
            float4 a = ((const float4*)Acc)[(size_t)gr * 32 + c4];
            hv = ((const float4*)H)[(size_t)gr * 32 + c4];
            const float4 bb = ((const float4*)ubias)[c4];
            hv.x += fmaxf(a.x * inv + bb.x, 0.f);
            hv.y += fmaxf(a.y * inv + bb.y, 0.f);
            hv.z += fmaxf(a.z * inv + bb.z, 0.f);
            hv.w += fmaxf(a.w * inv + bb.w, 0.f);
            ((float4*)H)[(size_t)gr * 32 + c4] = hv;
        }
        store_paired4(As + r * AP128, c4, hv);
    }
    __syncthreads();

    const int wid = tid >> 5, lane = tid & 31;
    const int wm = wid & 1, wn = wid >> 1;
    const int wrow = wm * 64, wcol = wn * 64;
    const int gid = lane >> 2, tig = lane & 3;

    float acc[4][8][4];
#pragma unroll
    for (int ph = 0; ph < 2; ++ph) {
        const float* Ws   = ph ? Ws1 : Ws0;
        const float* bias = ph ? br  : bl;
        float* C          = ph ? Cr  : Cl;
#pragma unroll
        for (int mf = 0; mf < 4; ++mf)
#pragma unroll
            for (int nf = 0; nf < 8; ++nf)
#pragma unroll
                for (int j = 0; j < 4; ++j) acc[mf][nf][j] = 0.f;
        mma_loop<4, 8, 16>(As, AP128, 0, Ws, wrow, wcol, gid, tig, acc);
#pragma unroll
        for (int nf = 0; nf < 8; ++nf) {
            const int c = wcol + nf * 8 + tig * 2;
            const float b0 = bias[c], b1 = bias[c + 1];
#pragma unroll
            for (int mf = 0; mf < 4; ++mf)
#pragma unroll
                for (int h = 0; h < 2; ++h) {
                    const int r = row0 + wrow + mf * 16 + h * 8 + gid;
                    if (r < M)
                        *(float2*)(C + (size_t)r * 128 + c) =
                            make_float2(acc[mf][nf][2 * h] + b0, acc[mf][nf][2 * h + 1] + b1);
                }
        }
    }
}

// ---------- fused edge pass ----------
__global__ void edge_kernel(const int* __restrict__ src, const int* __restrict__ dst,
                            const float* __restrict__ att)
{
    int e = (int)(((size_t)blockIdx.x * blockDim.x + threadIdx.x) >> 5);
    if (e >= NE) return;
    int ln = threadIdx.x & 31;
    int s = src[e], d = dst[e];
    float4 xa = ((const float4*)g_xl)[(size_t)s * 32 + ln];
    float4 xb = ((const float4*)g_xr)[(size_t)d * 32 + ln];
    float4 at = ((const float4*)att)[ln];
    float ex, ey, ez, ew;
    ex = xa.x + xb.x; ey = xa.y + xb.y; ez = xa.z + xb.z; ew = xa.w + xb.w;
    ex = ex > 0.f ? ex : 0.2f * ex;
    ey = ey > 0.f ? ey : 0.2f * ey;
    ez = ez > 0.f ? ez : 0.2f * ez;
    ew = ew > 0.f ? ew : 0.2f * ew;
    float p = ex * at.x + ey * at.y + ez * at.z + ew * at.w;
#pragma unroll
    for (int o = 16; o > 0; o >>= 1) p += __shfl_xor_sync(0xffffffffu, p, o);
    float e_ = __expf(p);
    if (ln == 0) atomicAdd(&g_den[d], e_);
    float* accd = g_acc + (size_t)d * 128 + ln * 4;
    atomicAdd(accd + 0, e_ * xa.x);
    atomicAdd(accd + 1, e_ * xa.y);
    atomicAdd(accd + 2, e_ * xa.z);
    atomicAdd(accd + 3, e_ * xa.w);
}

// ---------- mega head: BM=64, warp tile 64x32 ----------
__global__ __launch_bounds__(128, 1) void head_kernel(
    const float* __restrict__ H, const float* __restrict__ Acc, const float* __restrict__ Den,
    const float* __restrict__ ubias,
    const int* __restrict__ child, const int* __restrict__ parent,
    const float* __restrict__ ttab, const int* __restrict__ timei,
    const float* __restrict__ W_comb, const float* __restrict__ b_comb,
    const float* __restrict__ W_a1, const float* __restrict__ cadd,
    const float* __restrict__ W_a2, const float* __restrict__ b_a2,
    float* __restrict__ out, int M)
{
    extern __shared__ float sh[];
    float* As  = sh;                    // 64 x AP256
    float* Ws  = sh + 64 * AP256;       // 128 x WNP
    float* red = Ws + 128 * WNP;        // 4 x 64
    const int tid = threadIdx.x;
    const int row0 = blockIdx.x * 64;

    // stage cat(h2[child], h2[parent]|0), h2 = h1 + relu(acc/den + ubias)
    for (int i = tid; i < 64 * 64; i += 128) {
        int r = i >> 6, c4 = i & 63;
        int gr = row0 + r;
        float4 v = make_float4(0.f, 0.f, 0.f, 0.f);
        if (gr < M) {
            int cc = c4 < 32 ? c4 : c4 - 32;
            int ri = c4 < 32 ? child[gr] : parent[gr];
            if (ri >= 0) {
                float inv = 1.f / (Den[ri] + 1e-16f);
                float4 a  = ((const float4*)Acc)[(size_t)ri * 32 + cc];
                v         = ((const float4*)H)[(size_t)ri * 32 + cc];
                float4 bb = ((const float4*)ubias)[cc];
                v.x += fmaxf(a.x * inv + bb.x, 0.f);
                v.y += fmaxf(a.y * inv + bb.y, 0.f);
                v.z += fmaxf(a.z * inv + bb.z, 0.f);
                v.w += fmaxf(a.w * inv + bb.w, 0.f);
            }
        }
        store_paired4(As + r * AP256, c4, v);
    }

    const int wid = tid >> 5, lane = tid & 31;
    const int wcol = wid * 32;          // warp tile 64 rows x 32 cols
    const int gid = lane >> 2, tig = lane & 3;

    float acc[4][4][4];
#pragma unroll
    for (int mf = 0; mf < 4; ++mf)
#pragma unroll
        for (int nf = 0; nf < 4; ++nf)
#pragma unroll
            for (int j = 0; j < 4; ++j) acc[mf][nf][j] = 0.f;

    // GEMM1: branch = cat @ W_comb
    for (int kc = 0; kc < 2; ++kc) {
        __syncthreads();
        stage_w<128>(W_comb + kc * 128 * 128, Ws, tid);
        __syncthreads();
        mma_loop<4, 4, 16>(As, AP256, kc * 160, Ws, 0, wcol, gid, tig, acc);
    }
    __syncthreads();

    // epilogue1: branch(+b_comb) -> As k cols [0,128) paired
#pragma unroll
    for (int nf = 0; nf < 4; ++nf) {
        const int c = wcol + nf * 8 + tig * 2;
        const int ks = c >> 3, kk = c & 7;
        const int p0 = ((kk & 3) << 1) | (kk >> 2);
        const int p1 = (((kk + 1) & 3) << 1) | ((kk + 1) >> 2);
        const float b0 = b_comb[c], b1 = b_comb[c + 1];
#pragma unroll
        for (int mf = 0; mf < 4; ++mf)
#pragma unroll
            for (int h = 0; h < 2; ++h) {
                const int rl = mf * 16 + h * 8 + gid;
                float* ap = As + rl * AP256 + ks * 10;
                ap[p0] = tf32f(acc[mf][nf][2 * h]     + b0);
                ap[p1] = tf32f(acc[mf][nf][2 * h + 1] + b1);
            }
    }
    // stage t_emb -> As k cols [128,256) paired
    for (int i = tid; i < 64 * 32; i += 128) {
        int r = i >> 5, c4 = i & 31;
        int gr = row0 + r;
        float4 v = make_float4(0.f, 0.f, 0.f, 0.f);
        if (gr < M) {
            int t = timei[gr];
            v = ((const float4*)(ttab + (size_t)t * 128))[c4];
        }
        float* p = As + r * AP256 + (16 + (c4 >> 1)) * 10 + (c4 & 1);
        p[0] = tf32f(v.x); p[2] = tf32f(v.y); p[4] = tf32f(v.z); p[6] = tf32f(v.w);
    }

    // GEMM2: hidden = relu(cat @ W_a1 + cadd)
#pragma unroll
    for (int mf = 0; mf < 4; ++mf)
#pragma unroll
        for (int nf = 0; nf < 4; ++nf)
#pragma unroll
            for (int j = 0; j < 4; ++j) acc[mf][nf][j] = 0.f;
    for (int kc = 0; kc < 2; ++kc) {
        __syncthreads();
        stage_w<128>(W_a1 + kc * 128 * 128, Ws, tid);
        __syncthreads();
        mma_loop<4, 4, 16>(As, AP256, kc * 160, Ws, 0, wcol, gid, tig, acc);
    }

    // epilogue2: dot with W_a2
    float p[4][2];
#pragma unroll
    for (int mf = 0; mf < 4; ++mf) { p[mf][0] = 0.f; p[mf][1] = 0.f; }
#pragma unroll
    for (int nf = 0; nf < 4; ++nf) {
        const int c = wcol + nf * 8 + tig * 2;
        const float ca0 = cadd[c], ca1 = cadd[c + 1];
        const float w20 = W_a2[c], w21 = W_a2[c + 1];
#pragma unroll
        for (int mf = 0; mf < 4; ++mf)
#pragma unroll
            for (int h = 0; h < 2; ++h) {
                float v0 = fmaxf(acc[mf][nf][2 * h]     + ca0, 0.f);
                float v1 = fmaxf(acc[mf][nf][2 * h + 1] + ca1, 0.f);
                p[mf][h] += v0 * w20 + v1 * w21;
            }
    }
#pragma unroll
    for (int o = 1; o <= 2; o <<= 1)
#pragma unroll
        for (int mf = 0; mf < 4; ++mf)
#pragma unroll
            for (int h = 0; h < 2; ++h)
                p[mf][h] += __shfl_xor_sync(0xffffffffu, p[mf][h], o);

    __syncthreads();
    if (tig == 0) {
#pragma unroll
        for (int mf = 0; mf < 4; ++mf)
#pragma unroll
            for (int h = 0; h < 2; ++h)
                red[wid * 64 + mf * 16 + h * 8 + gid] = p[mf][h];
    }
    __syncthreads();
    if (tid < 64) {
        int gr = row0 + tid;
        if (gr < M)
            out[gr] = red[tid] + red[64 + tid] + red[128 + tid] + red[192 + tid] + b_a2[0];
    }
}

// ---------------- context precompute ----------------
__global__ void ctx_kernel(const float* __restrict__ focal, const float* __restrict__ W_seq,
                           const float* __restrict__ b_seq)
{
    int j = threadIdx.x;
    float s = b_seq[j];
    for (int d = 0; d < DD; ++d) s += focal[d] * W_seq[d * 128 + j];
    g_ctx[j] = s;
}

__global__ void cadd_kernel(const float* __restrict__ W_a1, const float* __restrict__ b_a1)
{
    int j = threadIdx.x;
    float s = b_a1[j];
    for (int k = 0; k < 128; ++k) s += g_ctx[k] * W_a1[(256 + k) * 128 + j];
    g_cadd[j] = s;
}

// ---------------- launch ----------------
extern "C" void kernel_launch(void* const* d_in, const int* in_sizes, int n_in,
                              void* d_out, int out_size)
{
    const float* x       = (const float*)d_in[0];
    const int*   ei      = (const int*)  d_in[1];
    const float* focal   = (const float*)d_in[2];
    const int*   child   = (const int*)  d_in[3];
    const int*   parent  = (const int*)  d_in[4];
    const int*   timei   = (const int*)  d_in[5];
    const float* W_embed = (const float*)d_in[6];
    const float* b_embed = (const float*)d_in[7];
    const float* bu_Wl   = (const float*)d_in[8];
    const float* bu_bl   = (const float*)d_in[9];
    const float* bu_Wr   = (const float*)d_in[10];
    const float* bu_br   = (const float*)d_in[11];
    const float* bu_att  = (const float*)d_in[12];
    const float* bu_bias = (const float*)d_in[13];
    const float* td_Wl   = (const float*)d_in[14];
    const float* td_bl   = (const float*)d_in[15];
    const float* td_Wr   = (const float*)d_in[16];
    const float* td_br   = (const float*)d_in[17];
    const float* td_att  = (const float*)d_in[18];
    const float* td_bias = (const float*)d_in[19];
    const float* ttab    = (const float*)d_in[20];
    const float* W_comb  = (const float*)d_in[21];
    const float* b_comb  = (const float*)d_in[22];
    const float* W_a1    = (const float*)d_in[23];
    const float* b_a1    = (const float*)d_in[24];
    const float* W_a2    = (const float*)d_in[25];
    const float* b_a2    = (const float*)d_in[26];
    const float* W_seq   = (const float*)d_in[27];
    const float* b_seq   = (const float*)d_in[28];
    float* out = (float*)d_out;

    const int SM_DUAL = (128 * AP128 + 2 * 128 * WNP) * 4;       // 223,232 B
    const int SM_HEAD = (64 * AP256 + 128 * WNP + 256) * 4;      // 153,600 B
    cudaFuncSetAttribute(embed_dual,  cudaFuncAttributeMaxDynamicSharedMemorySize, SM_DUAL);
    cudaFuncSetAttribute(dual_upd,    cudaFuncAttributeMaxDynamicSharedMemorySize, SM_DUAL);
    cudaFuncSetAttribute(head_kernel, cudaFuncAttributeMaxDynamicSharedMemorySize, SM_HEAD);

    float *hp, *xlp, *xrp, *accp, *denp, *caddp;
    cudaGetSymbolAddress((void**)&hp,    g_h);
    cudaGetSymbolAddress((void**)&xlp,   g_xl);
    cudaGetSymbolAddress((void**)&xrp,   g_xr);
    cudaGetSymbolAddress((void**)&accp,  g_acc);
    cudaGetSymbolAddress((void**)&denp,  g_den);
    cudaGetSymbolAddress((void**)&caddp, g_cadd);

    const int GEMM_BLKS_N = (NN + 127) / 128;
    const int HEAD_BLKS   = (NA + 63) / 64;
    const int EDGE_BLKS   = (NE + 7) / 8;

    // 1) embed + bottom-up transforms (src = row1, dst = row0)
    embed_dual<<<GEMM_BLKS_N, 128, SM_DUAL>>>(x, W_embed, b_embed,
                                              bu_Wl, bu_bl, bu_Wr, bu_br,
                                              hp, xlp, xrp, NN);
    cudaMemsetAsync(accp, 0, (size_t)NN * HH * 4);
    cudaMemsetAsync(denp, 0, (size_t)NN * 4);
    edge_kernel<<<EDGE_BLKS, 256>>>(ei + NE, ei, bu_att);

    // 2) update1 fused + top-down transforms (src = row0, dst = row1)
    dual_upd<<<GEMM_BLKS_N, 128, SM_DUAL>>>(hp, accp, denp, bu_bias,
                                            td_Wl, td_bl, td_Wr, td_br,
                                            xlp, xrp, NN);
    cudaMemsetAsync(accp, 0, (size_t)NN * HH * 4);
    cudaMemsetAsync(denp, 0, (size_t)NN * 4);
    edge_kernel<<<EDGE_BLKS, 256>>>(ei, ei + NE, td_att);

    // 3) context fold
    ctx_kernel<<<1, 128>>>(focal, W_seq, b_seq);
    cadd_kernel<<<1, 128>>>(W_a1, b_a1);

    // 4) head with on-the-fly update2
    head_kernel<<<HEAD_BLKS, 128, SM_HEAD>>>(hp, accp, denp, td_bias,
                                             child, parent, ttab, timei,
                                             W_comb, b_comb, W_a1, caddp,
                                             W_a2, b_a2, out, NA);
}

// round 6
// speedup vs baseline: 1.3116x; 1.3116x over previous
#include <cuda_runtime.h>
#include <math.h>
#include <stdint.h>

#define NN   300000
#define NE   299999
#define NA   150000
#define DD   64
#define HH   128

// ---------------- scratch ----------------
__device__ float g_h   [(size_t)NN * HH];
__device__ float g_xl  [(size_t)NN * HH];
__device__ float g_xr  [(size_t)NN * HH];
__device__ float g_acc [(size_t)NN * HH];
__device__ float g_den [NN];
__device__ float g_ctx [HH];
__device__ float g_cadd[HH];

// ---------------- tf32 helpers ----------------
__device__ __forceinline__ uint32_t f2tf32(float f)
{
    uint32_t u;
    asm("cvt.rna.tf32.f32 %0, %1;" : "=r"(u) : "f"(f));
    return u;
}
__device__ __forceinline__ float tf32f(float f) { return __uint_as_float(f2tf32(f)); }

__device__ __forceinline__ void mma_tf32(float* d, const uint32_t* a, const uint32_t* b)
{
    asm volatile(
        "mma.sync.aligned.m16n8k8.row.col.f32.tf32.tf32.f32 "
        "{%0,%1,%2,%3},{%4,%5,%6,%7},{%8,%9},{%0,%1,%2,%3};"
        : "+f"(d[0]), "+f"(d[1]), "+f"(d[2]), "+f"(d[3])
        : "r"(a[0]), "r"(a[1]), "r"(a[2]), "r"(a[3]), "r"(b[0]), "r"(b[1]));
}

#define WNP   136        // W smem pitch [k][n] (b loads conflict-free)
#define AP64  82         // A pitch K=64  (8 kchunks*10 + 2;  ≡18 mod 64)
#define AP128 164        // A pitch K=128 (16 kchunks*10 + 4; ≡36 mod 64)
#define AP256 338        // A pitch K=256 (32 kchunks*10 + 18; ≡18 mod 64)

// paired-k layout: within an 8-k chunk, order [0,4,1,5,2,6,3,7]:
// p(kk) = 2*(kk&3) + (kk>>2). Pair (tig, tig+4) adjacent -> one LDS.64.

template <int MF, int NF, int NK>
__device__ __forceinline__ void mma_loop(
    const float* As, int apitch, int aoff, const float* Ws,
    int wrow, int wcol, int gid, int tig, float acc[MF][NF][4])
{
#pragma unroll
    for (int ks = 0; ks < NK; ++ks) {
        const int k0 = ks * 8;
        uint32_t a[MF][4], b[NF][2];
#pragma unroll
        for (int mf = 0; mf < MF; ++mf) {
            const float* ap = As + (wrow + mf * 16 + gid) * apitch + aoff + ks * 10 + 2 * tig;
            float2 lo = *(const float2*)ap;
            float2 hi = *(const float2*)(ap + 8 * apitch);
            a[mf][0] = __float_as_uint(lo.x);
            a[mf][1] = __float_as_uint(hi.x);
            a[mf][2] = __float_as_uint(lo.y);
            a[mf][3] = __float_as_uint(hi.y);
        }
#pragma unroll
        for (int nf = 0; nf < NF; ++nf) {
            const int c = wcol + nf * 8 + gid;
            b[nf][0] = __float_as_uint(Ws[(k0 + tig) * WNP + c]);
            b[nf][1] = __float_as_uint(Ws[(k0 + tig + 4) * WNP + c]);
        }
#pragma unroll
        for (int mf = 0; mf < MF; ++mf)
#pragma unroll
            for (int nf = 0; nf < NF; ++nf)
                mma_tf32(acc[mf][nf], a[mf], b[nf]);
    }
}

// stage W [K x 128] -> Ws [k][n] pitch WNP (256-thread block)
template <int K>
__device__ __forceinline__ void stage_w(const float* __restrict__ W, float* Ws, int tid)
{
    for (int i = tid; i < K * 32; i += 256) {
        int k = i >> 5, c4 = i & 31;
        float4 v = ((const float4*)W)[i];
        float* wp = Ws + k * WNP + c4 * 4;
        wp[0] = tf32f(v.x); wp[1] = tf32f(v.y); wp[2] = tf32f(v.z); wp[3] = tf32f(v.w);
    }
}

// write float4 of 4 consecutive k (k = 4*c4..4*c4+3) into paired layout
__device__ __forceinline__ void store_paired4(float* base, int c4, float4 v)
{
    float* p = base + (c4 >> 1) * 10 + (c4 & 1);
    p[0] = tf32f(v.x); p[2] = tf32f(v.y); p[4] = tf32f(v.z); p[6] = tf32f(v.w);
}

#define ZACC(acc, MF, NF)                        \
    _Pragma("unroll") for (int mf = 0; mf < MF; ++mf) \
    _Pragma("unroll") for (int nf = 0; nf < NF; ++nf) \
    _Pragma("unroll") for (int j = 0; j < 4; ++j) acc[mf][nf][j] = 0.f;

// ---------- fused embed + dual transform ----------
__global__ __launch_bounds__(256, 1) void embed_dual(
    const float* __restrict__ x,
    const float* __restrict__ We, const float* __restrict__ be,
    const float* __restrict__ Wl, const float* __restrict__ bl,
    const float* __restrict__ Wr, const float* __restrict__ br,
    float* __restrict__ Hout, float* __restrict__ Cl, float* __restrict__ Cr, int M)
{
    extern __shared__ float sh[];
    float* As  = sh;                       // 128 x AP128 (phase A: pitch AP64)
    float* Ws0 = sh + 128 * AP128;
    float* Ws1 = Ws0 + 128 * WNP;
    const int tid = threadIdx.x;
    const int row0 = blockIdx.x * 128;

    stage_w<64>(We, Ws0, tid);
    for (int i = tid; i < 128 * 16; i += 256) {
        int r = i >> 4, c4 = i & 15;
        int gr = row0 + r;
        float4 v = make_float4(0.f, 0.f, 0.f, 0.f);
        if (gr < M) v = ((const float4*)(x + (size_t)gr * 64))[c4];
        store_paired4(As + r * AP64, c4, v);
    }
    __syncthreads();

    const int wid = tid >> 5, lane = tid & 31;
    const int wm = wid & 1, wn = wid >> 1;       // 2x4 warp grid, tile 64x32
    const int wrow = wm * 64, wcol = wn * 32;
    const int gid = lane >> 2, tig = lane & 3;

    float acc[4][4][4];
    ZACC(acc, 4, 4)
    mma_loop<4, 4, 8>(As, AP64, 0, Ws0, wrow, wcol, gid, tig, acc);
    __syncthreads();   // phase-A reads complete before overwrite

    // epilogue h: write gmem + restage paired into As (pitch AP128)
#pragma unroll
    for (int nf = 0; nf < 4; ++nf) {
        const int c = wcol + nf * 8 + tig * 2;
        const int ks = c >> 3, kk = c & 7;
        const int p0 = ((kk & 3) << 1) | (kk >> 2);
        const int p1 = (((kk + 1) & 3) << 1) | ((kk + 1) >> 2);
        const float b0 = be[c], b1 = be[c + 1];
#pragma unroll
        for (int mf = 0; mf < 4; ++mf)
#pragma unroll
            for (int h = 0; h < 2; ++h) {
                const int rl = wrow + mf * 16 + h * 8 + gid;
                const float v0 = acc[mf][nf][2 * h] + b0;
                const float v1 = acc[mf][nf][2 * h + 1] + b1;
                const int gr = row0 + rl;
                if (gr < M)
                    *(float2*)(Hout + (size_t)gr * 128 + c) = make_float2(v0, v1);
                float* ap = As + rl * AP128 + ks * 10;
                ap[p0] = tf32f(v0);
                ap[p1] = tf32f(v1);
            }
    }
    stage_w<128>(Wl, Ws0, tid);
    stage_w<128>(Wr, Ws1, tid);
    __syncthreads();

#pragma unroll
    for (int ph = 0; ph < 2; ++ph) {
        const float* Ws   = ph ? Ws1 : Ws0;
        const float* bias = ph ? br  : bl;
        float* C          = ph ? Cr  : Cl;
        ZACC(acc, 4, 4)
        mma_loop<4, 4, 16>(As, AP128, 0, Ws, wrow, wcol, gid, tig, acc);
#pragma unroll
        for (int nf = 0; nf < 4; ++nf) {
            const int c = wcol + nf * 8 + tig * 2;
            const float b0 = bias[c], b1 = bias[c + 1];
#pragma unroll
            for (int mf = 0; mf < 4; ++mf)
#pragma unroll
                for (int h = 0; h < 2; ++h) {
                    const int r = row0 + wrow + mf * 16 + h * 8 + gid;
                    if (r < M)
                        *(float2*)(C + (size_t)r * 128 + c) =
                            make_float2(acc[mf][nf][2 * h] + b0, acc[mf][nf][2 * h + 1] + b1);
                }
        }
    }
}

// ---------- dual transform with fused update ----------
__global__ __launch_bounds__(256, 1) void dual_upd(
    float* __restrict__ H, const float* __restrict__ Acc, const float* __restrict__ Den,
    const float* __restrict__ ubias,
    const float* __restrict__ Wl, const float* __restrict__ bl,
    const float* __restrict__ Wr, const float* __restrict__ br,
    float* __restrict__ Cl, float* __restrict__ Cr, int M)
{
    extern __shared__ float sh[];
    float* As  = sh;
    float* Ws0 = sh + 128 * AP128;
    float* Ws1 = Ws0 + 128 * WNP;
    const int tid = threadIdx.x;
    const int row0 = blockIdx.x * 128;

    stage_w<128>(Wl, Ws0, tid);
    stage_w<128>(Wr, Ws1, tid);

    for (int i = tid; i < 128 * 32; i += 256) {
        int r = i >> 5, c4 = i & 31;
        int gr = row0 + r;
        float4 hv = make_float4(0.f, 0.f, 0.f, 0.f);
        if (gr < M) {
            float inv = 1.f / (Den[gr] + 1e-16f);
            float4 a = ((const float4*)Acc)[(size_t)gr * 32 + c4];
            hv = ((const float4*)H)[(size_t)gr * 32 + c4];
            const float4 bb = ((const float4*)ubias)[c4];
            hv.x += fmaxf(a.x * inv + bb.x, 0.f);
            hv.y += fmaxf(a.y * inv + bb.y, 0.f);
            hv.z += fmaxf(a.z * inv + bb.z, 0.f);
            hv.w += fmaxf(a.w * inv + bb.w, 0.f);
            ((float4*)H)[(size_t)gr * 32 + c4] = hv;
        }
        store_paired4(As + r * AP128, c4, hv);
    }
    __syncthreads();

    const int wid = tid >> 5, lane = tid & 31;
    const int wm = wid & 1, wn = wid >> 1;
    const int wrow = wm * 64, wcol = wn * 32;
    const int gid = lane >> 2, tig = lane & 3;

    float acc[4][4][4];
#pragma unroll
    for (int ph = 0; ph < 2; ++ph) {
        const float* Ws   = ph ? Ws1 : Ws0;
        const float* bias = ph ? br  : bl;
        float* C          = ph ? Cr  : Cl;
        ZACC(acc, 4, 4)
        mma_loop<4, 4, 16>(As, AP128, 0, Ws, wrow, wcol, gid, tig, acc);
#pragma unroll
        for (int nf = 0; nf < 4; ++nf) {
            const int c = wcol + nf * 8 + tig * 2;
            const float b0 = bias[c], b1 = bias[c + 1];
#pragma unroll
            for (int mf = 0; mf < 4; ++mf)
#pragma unroll
                for (int h = 0; h < 2; ++h) {
                    const int r = row0 + wrow + mf * 16 + h * 8 + gid;
                    if (r < M)
                        *(float2*)(C + (size_t)r * 128 + c) =
                            make_float2(acc[mf][nf][2 * h] + b0, acc[mf][nf][2 * h + 1] + b1);
                }
        }
    }
}

// ---------- fused edge pass ----------
__global__ void edge_kernel(const int* __restrict__ src, const int* __restrict__ dst,
                            const float* __restrict__ att)
{
    int e = (int)(((size_t)blockIdx.x * blockDim.x + threadIdx.x) >> 5);
    if (e >= NE) return;
    int ln = threadIdx.x & 31;
    int s = src[e], d = dst[e];
    float4 xa = ((const float4*)g_xl)[(size_t)s * 32 + ln];
    float4 xb = ((const float4*)g_xr)[(size_t)d * 32 + ln];
    float4 at = ((const float4*)att)[ln];
    float ex, ey, ez, ew;
    ex = xa.x + xb.x; ey = xa.y + xb.y; ez = xa.z + xb.z; ew = xa.w + xb.w;
    ex = ex > 0.f ? ex : 0.2f * ex;
    ey = ey > 0.f ? ey : 0.2f * ey;
    ez = ez > 0.f ? ez : 0.2f * ez;
    ew = ew > 0.f ? ew : 0.2f * ew;
    float p = ex * at.x + ey * at.y + ez * at.z + ew * at.w;
#pragma unroll
    for (int o = 16; o > 0; o >>= 1) p += __shfl_xor_sync(0xffffffffu, p, o);
    float e_ = __expf(p);
    if (ln == 0) atomicAdd(&g_den[d], e_);
    float* accd = g_acc + (size_t)d * 128 + ln * 4;
    atomicAdd(accd + 0, e_ * xa.x);
    atomicAdd(accd + 1, e_ * xa.y);
    atomicAdd(accd + 2, e_ * xa.z);
    atomicAdd(accd + 3, e_ * xa.w);
}

// ---------- mega head: BM=128, warp tile 64x32, W staged in 64-row chunks ----------
__global__ __launch_bounds__(256, 1) void head_kernel(
    const float* __restrict__ H, const float* __restrict__ Acc, const float* __restrict__ Den,
    const float* __restrict__ ubias,
    const int* __restrict__ child, const int* __restrict__ parent,
    const float* __restrict__ ttab, const int* __restrict__ timei,
    const float* __restrict__ W_comb, const float* __restrict__ b_comb,
    const float* __restrict__ W_a1, const float* __restrict__ cadd,
    const float* __restrict__ W_a2, const float* __restrict__ b_a2,
    float* __restrict__ out, int M)
{
    extern __shared__ float sh[];
    float* As  = sh;                    // 128 x AP256
    float* Ws  = sh + 128 * AP256;      // 64 x WNP
    float* red = Ws + 64 * WNP;         // 4 x 128
    const int tid = threadIdx.x;
    const int row0 = blockIdx.x * 128;

    // stage cat(h2[child], h2[parent]|0), h2 = h1 + relu(acc/den + ubias)
    for (int i = tid; i < 128 * 64; i += 256) {
        int r = i >> 6, c4 = i & 63;
        int gr = row0 + r;
        float4 v = make_float4(0.f, 0.f, 0.f, 0.f);
        if (gr < M) {
            int cc = c4 < 32 ? c4 : c4 - 32;
            int ri = c4 < 32 ? child[gr] : parent[gr];
            if (ri >= 0) {
                float inv = 1.f / (Den[ri] + 1e-16f);
                float4 a  = ((const float4*)Acc)[(size_t)ri * 32 + cc];
                v         = ((const float4*)H)[(size_t)ri * 32 + cc];
                float4 bb = ((const float4*)ubias)[cc];
                v.x += fmaxf(a.x * inv + bb.x, 0.f);
                v.y += fmaxf(a.y * inv + bb.y, 0.f);
                v.z += fmaxf(a.z * inv + bb.z, 0.f);
                v.w += fmaxf(a.w * inv + bb.w, 0.f);
            }
        }
        store_paired4(As + r * AP256, c4, v);
    }

    const int wid = tid >> 5, lane = tid & 31;
    const int wm = wid & 1, wn = wid >> 1;
    const int wrow = wm * 64, wcol = wn * 32;
    const int gid = lane >> 2, tig = lane & 3;

    float acc[4][4][4];
    ZACC(acc, 4, 4)

    // GEMM1: branch = cat @ W_comb  (K=256 in 4 chunks of 64)
    for (int kc = 0; kc < 4; ++kc) {
        __syncthreads();
        stage_w<64>(W_comb + kc * 64 * 128, Ws, tid);
        __syncthreads();
        mma_loop<4, 4, 8>(As, AP256, kc * 80, Ws, wrow, wcol, gid, tig, acc);
    }
    __syncthreads();

    // epilogue1: branch(+b_comb) -> As k cols [0,128) paired
#pragma unroll
    for (int nf = 0; nf < 4; ++nf) {
        const int c = wcol + nf * 8 + tig * 2;
        const int ks = c >> 3, kk = c & 7;
        const int p0 = ((kk & 3) << 1) | (kk >> 2);
        const int p1 = (((kk + 1) & 3) << 1) | ((kk + 1) >> 2);
        const float b0 = b_comb[c], b1 = b_comb[c + 1];
#pragma unroll
        for (int mf = 0; mf < 4; ++mf)
#pragma unroll
            for (int h = 0; h < 2; ++h) {
                const int rl = wrow + mf * 16 + h * 8 + gid;
                float* ap = As + rl * AP256 + ks * 10;
                ap[p0] = tf32f(acc[mf][nf][2 * h]     + b0);
                ap[p1] = tf32f(acc[mf][nf][2 * h + 1] + b1);
            }
    }
    // stage t_emb -> As k cols [128,256) paired
    for (int i = tid; i < 128 * 32; i += 256) {
        int r = i >> 5, c4 = i & 31;
        int gr = row0 + r;
        float4 v = make_float4(0.f, 0.f, 0.f, 0.f);
        if (gr < M) {
            int t = timei[gr];
            v = ((const float4*)(ttab + (size_t)t * 128))[c4];
        }
        float* p = As + r * AP256 + (16 + (c4 >> 1)) * 10 + (c4 & 1);
        p[0] = tf32f(v.x); p[2] = tf32f(v.y); p[4] = tf32f(v.z); p[6] = tf32f(v.w);
    }

    // GEMM2: hidden = relu(cat @ W_a1 + cadd)
    float acc2[4][4][4];
    ZACC(acc2, 4, 4)
    for (int kc = 0; kc < 4; ++kc) {
        __syncthreads();
        stage_w<64>(W_a1 + kc * 64 * 128, Ws, tid);
        __syncthreads();
        mma_loop<4, 4, 8>(As, AP256, kc * 80, Ws, wrow, wcol, gid, tig, acc2);
    }

    // epilogue2: dot with W_a2
    float p[4][2];
#pragma unroll
    for (int mf = 0; mf < 4; ++mf) { p[mf][0] = 0.f; p[mf][1] = 0.f; }
#pragma unroll
    for (int nf = 0; nf < 4; ++nf) {
        const int c = wcol + nf * 8 + tig * 2;
        const float ca0 = cadd[c], ca1 = cadd[c + 1];
        const float w20 = W_a2[c], w21 = W_a2[c + 1];
#pragma unroll
        for (int mf = 0; mf < 4; ++mf)
#pragma unroll
            for (int h = 0; h < 2; ++h) {
                float v0 = fmaxf(acc2[mf][nf][2 * h]     + ca0, 0.f);
                float v1 = fmaxf(acc2[mf][nf][2 * h + 1] + ca1, 0.f);
                p[mf][h] += v0 * w20 + v1 * w21;
            }
    }
#pragma unroll
    for (int o = 1; o <= 2; o <<= 1)
#pragma unroll
        for (int mf = 0; mf < 4; ++mf)
#pragma unroll
            for (int h = 0; h < 2; ++h)
                p[mf][h] += __shfl_xor_sync(0xffffffffu, p[mf][h], o);

    __syncthreads();
    if (tig == 0) {
#pragma unroll
        for (int mf = 0; mf < 4; ++mf)
#pragma unroll
            for (int h = 0; h < 2; ++h)
                red[wn * 128 + wrow + mf * 16 + h * 8 + gid] = p[mf][h];
    }
    __syncthreads();
    if (tid < 128) {
        int gr = row0 + tid;
        if (gr < M)
            out[gr] = red[tid] + red[128 + tid] + red[256 + tid] + red[384 + tid] + b_a2[0];
    }
}

// ---------------- context precompute ----------------
__global__ void ctx_kernel(const float* __restrict__ focal, const float* __restrict__ W_seq,
                           const float* __restrict__ b_seq)
{
    int j = threadIdx.x;
    float s = b_seq[j];
    for (int d = 0; d < DD; ++d) s += focal[d] * W_seq[d * 128 + j];
    g_ctx[j] = s;
}

__global__ void cadd_kernel(const float* __restrict__ W_a1, const float* __restrict__ b_a1)
{
    int j = threadIdx.x;
    float s = b_a1[j];
    for (int k = 0; k < 128; ++k) s += g_ctx[k] * W_a1[(256 + k) * 128 + j];
    g_cadd[j] = s;
}

// ---------------- launch ----------------
extern "C" void kernel_launch(void* const* d_in, const int* in_sizes, int n_in,
                              void* d_out, int out_size)
{
    const float* x       = (const float*)d_in[0];
    const int*   ei      = (const int*)  d_in[1];
    const float* focal   = (const float*)d_in[2];
    const int*   child   = (const int*)  d_in[3];
    const int*   parent  = (const int*)  d_in[4];
    const int*   timei   = (const int*)  d_in[5];
    const float* W_embed = (const float*)d_in[6];
    const float* b_embed = (const float*)d_in[7];
    const float* bu_Wl   = (const float*)d_in[8];
    const float* bu_bl   = (const float*)d_in[9];
    const float* bu_Wr   = (const float*)d_in[10];
    const float* bu_br   = (const float*)d_in[11];
    const float* bu_att  = (const float*)d_in[12];
    const float* bu_bias = (const float*)d_in[13];
    const float* td_Wl   = (const float*)d_in[14];
    const float* td_bl   = (const float*)d_in[15];
    const float* td_Wr   = (const float*)d_in[16];
    const float* td_br   = (const float*)d_in[17];
    const float* td_att  = (const float*)d_in[18];
    const float* td_bias = (const float*)d_in[19];
    const float* ttab    = (const float*)d_in[20];
    const float* W_comb  = (const float*)d_in[21];
    const float* b_comb  = (const float*)d_in[22];
    const float* W_a1    = (const float*)d_in[23];
    const float* b_a1    = (const float*)d_in[24];
    const float* W_a2    = (const float*)d_in[25];
    const float* b_a2    = (const float*)d_in[26];
    const float* W_seq   = (const float*)d_in[27];
    const float* b_seq   = (const float*)d_in[28];
    float* out = (float*)d_out;

    const int SM_DUAL = (128 * AP128 + 2 * 128 * WNP) * 4;       // 223,232 B
    const int SM_HEAD = (128 * AP256 + 64 * WNP + 512) * 4;      // 209,920 B
    cudaFuncSetAttribute(embed_dual,  cudaFuncAttributeMaxDynamicSharedMemorySize, SM_DUAL);
    cudaFuncSetAttribute(dual_upd,    cudaFuncAttributeMaxDynamicSharedMemorySize, SM_DUAL);
    cudaFuncSetAttribute(head_kernel, cudaFuncAttributeMaxDynamicSharedMemorySize, SM_HEAD);

    float *hp, *xlp, *xrp, *accp, *denp, *caddp;
    cudaGetSymbolAddress((void**)&hp,    g_h);
    cudaGetSymbolAddress((void**)&xlp,   g_xl);
    cudaGetSymbolAddress((void**)&xrp,   g_xr);
    cudaGetSymbolAddress((void**)&accp,  g_acc);
    cudaGetSymbolAddress((void**)&denp,  g_den);
    cudaGetSymbolAddress((void**)&caddp, g_cadd);

    const int GEMM_BLKS_N = (NN + 127) / 128;
    const int HEAD_BLKS   = (NA + 127) / 128;
    const int EDGE_BLKS   = (NE + 7) / 8;

    // 1) embed + bottom-up transforms (src = row1, dst = row0)
    embed_dual<<<GEMM_BLKS_N, 256, SM_DUAL>>>(x, W_embed, b_embed,
                                              bu_Wl, bu_bl, bu_Wr, bu_br,
                                              hp, xlp, xrp, NN);
    cudaMemsetAsync(accp, 0, (size_t)NN * HH * 4);
    cudaMemsetAsync(denp, 0, (size_t)NN * 4);
    edge_kernel<<<EDGE_BLKS, 256>>>(ei + NE, ei, bu_att);

    // 2) update1 fused + top-down transforms (src = row0, dst = row1)
    dual_upd<<<GEMM_BLKS_N, 256, SM_DUAL>>>(hp, accp, denp, bu_bias,
                                            td_Wl, td_bl, td_Wr, td_br,
                                            xlp, xrp, NN);
    cudaMemsetAsync(accp, 0, (size_t)NN * HH * 4);
    cudaMemsetAsync(denp, 0, (size_t)NN * 4);
    edge_kernel<<<EDGE_BLKS, 256>>>(ei, ei + NE, td_att);

    // 3) context fold
    ctx_kernel<<<1, 128>>>(focal, W_seq, b_seq);
    cadd_kernel<<<1, 128>>>(W_a1, b_a1);

    // 4) head with on-the-fly update2
    head_kernel<<<HEAD_BLKS, 256, SM_HEAD>>>(hp, accp, denp, td_bias,
                                             child, parent, ttab, timei,
                                             W_comb, b_comb, W_a1, caddp,
                                             W_a2, b_a2, out, NA);
}

// round 7
// speedup vs baseline: 1.4309x; 1.0909x over previous
#include <cuda_runtime.h>
#include <math.h>
#include <stdint.h>

#define NN   300000
#define NE   299999
#define NA   150000
#define DD   64
#define HH   128

// ---------------- scratch ----------------
__device__ float g_h   [(size_t)NN * HH];
__device__ float g_xl  [(size_t)NN * HH];
__device__ float g_xr  [(size_t)NN * HH];
__device__ float g_acc [(size_t)NN * HH];
__device__ float g_den [NN];
__device__ float g_cadd[HH];

// ---------------- tf32 helpers ----------------
__device__ __forceinline__ uint32_t f2tf32(float f)
{
    uint32_t u;
    asm("cvt.rna.tf32.f32 %0, %1;" : "=r"(u) : "f"(f));
    return u;
}
__device__ __forceinline__ float tf32f(float f) { return __uint_as_float(f2tf32(f)); }

__device__ __forceinline__ void mma_tf32(float* d, const uint32_t* a, const uint32_t* b)
{
    asm volatile(
        "mma.sync.aligned.m16n8k8.row.col.f32.tf32.tf32.f32 "
        "{%0,%1,%2,%3},{%4,%5,%6,%7},{%8,%9},{%0,%1,%2,%3};"
        : "+f"(d[0]), "+f"(d[1]), "+f"(d[2]), "+f"(d[3])
        : "r"(a[0]), "r"(a[1]), "r"(a[2]), "r"(a[3]), "r"(b[0]), "r"(b[1]));
}

#define BM  128
#define WNP 136
#define AP  132   // A pitch for K=128 staging

__device__ __forceinline__ void zero_acc(float acc[2][8][4])
{
#pragma unroll
    for (int mf = 0; mf < 2; ++mf)
#pragma unroll
        for (int nf = 0; nf < 8; ++nf)
#pragma unroll
            for (int j = 0; j < 4; ++j) acc[mf][nf][j] = 0.f;
}

__device__ __forceinline__ void mma_block_128(
    const float* As, int KP, int a_off, const float* Ws,
    int wm, int wn, int gid, int tig, float acc[2][8][4])
{
#pragma unroll
    for (int ks = 0; ks < 16; ++ks) {
        const int k0 = ks * 8;
        uint32_t a[2][4], b[8][2];
#pragma unroll
        for (int mf = 0; mf < 2; ++mf) {
            const float* ap = As + (wm * 32 + mf * 16 + gid) * KP + a_off + k0;
            a[mf][0] = __float_as_uint(ap[tig]);
            a[mf][1] = __float_as_uint(ap[8 * KP + tig]);
            a[mf][2] = __float_as_uint(ap[tig + 4]);
            a[mf][3] = __float_as_uint(ap[8 * KP + tig + 4]);
        }
#pragma unroll
        for (int nf = 0; nf < 8; ++nf) {
            const int c = wn * 64 + nf * 8 + gid;
            b[nf][0] = __float_as_uint(Ws[(k0 + tig) * WNP + c]);
            b[nf][1] = __float_as_uint(Ws[(k0 + tig + 4) * WNP + c]);
        }
#pragma unroll
        for (int mf = 0; mf < 2; ++mf)
#pragma unroll
            for (int nf = 0; nf < 8; ++nf)
                mma_tf32(acc[mf][nf], a[mf], b[nf]);
    }
}

__device__ __forceinline__ void stage_w128(const float* __restrict__ W, float* Ws, int tid)
{
    for (int i = tid; i < 128 * 32; i += 256) {
        int k = i >> 5, c4 = i & 31;
        float4 v = ((const float4*)W)[i];
        float* wp = Ws + k * WNP + c4 * 4;
        wp[0] = tf32f(v.x); wp[1] = tf32f(v.y); wp[2] = tf32f(v.z); wp[3] = tf32f(v.w);
    }
}

// ---------- fused embed + dual transform ----------
__global__ __launch_bounds__(256) void embed_dual(
    const float* __restrict__ x,
    const float* __restrict__ We, const float* __restrict__ be,
    const float* __restrict__ Wl, const float* __restrict__ bl,
    const float* __restrict__ Wr, const float* __restrict__ br,
    float* __restrict__ Hout, float* __restrict__ Cl, float* __restrict__ Cr, int M)
{
    extern __shared__ float sh[];
    float* As  = sh;                       // BM x AP (phase A uses pitch 68)
    float* Ws0 = sh + BM * AP;
    float* Ws1 = Ws0 + 128 * WNP;
    const int tid = threadIdx.x;
    const int row0 = blockIdx.x * BM;

    for (int i = tid; i < 64 * 32; i += 256) {
        int k = i >> 5, c4 = i & 31;
        float4 v = ((const float4*)We)[i];
        float* wp = Ws0 + k * WNP + c4 * 4;
        wp[0] = tf32f(v.x); wp[1] = tf32f(v.y); wp[2] = tf32f(v.z); wp[3] = tf32f(v.w);
    }
    for (int i = tid; i < BM * 16; i += 256) {
        int r = i >> 4, c4 = i & 15;
        int gr = row0 + r;
        float4 v = make_float4(0.f, 0.f, 0.f, 0.f);
        if (gr < M) v = ((const float4*)(x + (size_t)gr * 64))[c4];
        float* ap = As + r * 68 + c4 * 4;
        ap[0] = tf32f(v.x); ap[1] = tf32f(v.y); ap[2] = tf32f(v.z); ap[3] = tf32f(v.w);
    }
    __syncthreads();

    const int wid = tid >> 5, lane = tid & 31;
    const int wm = wid & 3, wn = wid >> 2;
    const int gid = lane >> 2, tig = lane & 3;

    float acc[2][8][4];
    zero_acc(acc);
#pragma unroll
    for (int ks = 0; ks < 8; ++ks) {
        const int k0 = ks * 8;
        uint32_t a[2][4], b[8][2];
#pragma unroll
        for (int mf = 0; mf < 2; ++mf) {
            const float* ap = As + (wm * 32 + mf * 16 + gid) * 68 + k0;
            a[mf][0] = __float_as_uint(ap[tig]);
            a[mf][1] = __float_as_uint(ap[8 * 68 + tig]);
            a[mf][2] = __float_as_uint(ap[tig + 4]);
            a[mf][3] = __float_as_uint(ap[8 * 68 + tig + 4]);
        }
#pragma unroll
        for (int nf = 0; nf < 8; ++nf) {
            const int c = wn * 64 + nf * 8 + gid;
            b[nf][0] = __float_as_uint(Ws0[(k0 + tig) * WNP + c]);
            b[nf][1] = __float_as_uint(Ws0[(k0 + tig + 4) * WNP + c]);
        }
#pragma unroll
        for (int mf = 0; mf < 2; ++mf)
#pragma unroll
            for (int nf = 0; nf < 8; ++nf)
                mma_tf32(acc[mf][nf], a[mf], b[nf]);
    }
    __syncthreads();   // all reads of As/Ws0 complete

    // epilogue h: write gmem + restage tf32 into As (pitch AP)
#pragma unroll
    for (int nf = 0; nf < 8; ++nf) {
        const int c = wn * 64 + nf * 8 + tig * 2;
        const float b0 = be[c], b1 = be[c + 1];
#pragma unroll
        for (int mf = 0; mf < 2; ++mf)
#pragma unroll
            for (int h = 0; h < 2; ++h) {
                const int rl = wm * 32 + mf * 16 + h * 8 + gid;
                const float v0 = acc[mf][nf][2 * h] + b0;
                const float v1 = acc[mf][nf][2 * h + 1] + b1;
                const int gr = row0 + rl;
                if (gr < M)
                    *(float2*)(Hout + (size_t)gr * 128 + c) = make_float2(v0, v1);
                As[rl * AP + c]     = tf32f(v0);
                As[rl * AP + c + 1] = tf32f(v1);
            }
    }
    stage_w128(Wl, Ws0, tid);
    stage_w128(Wr, Ws1, tid);
    __syncthreads();

#pragma unroll
    for (int ph = 0; ph < 2; ++ph) {
        const float* Ws   = ph ? Ws1 : Ws0;
        const float* bias = ph ? br  : bl;
        float* C          = ph ? Cr  : Cl;
        zero_acc(acc);
        mma_block_128(As, AP, 0, Ws, wm, wn, gid, tig, acc);
#pragma unroll
        for (int nf = 0; nf < 8; ++nf) {
            const int c = wn * 64 + nf * 8 + tig * 2;
            const float b0 = bias[c], b1 = bias[c + 1];
#pragma unroll
            for (int mf = 0; mf < 2; ++mf)
#pragma unroll
                for (int h = 0; h < 2; ++h) {
                    const int r = row0 + wm * 32 + mf * 16 + h * 8 + gid;
                    if (r < M)
                        *(float2*)(C + (size_t)r * 128 + c) =
                            make_float2(acc[mf][nf][2 * h] + b0, acc[mf][nf][2 * h + 1] + b1);
                }
        }
    }
}

// ---------- dual transform with fused update: h1 = h + relu(acc/den + ubias) ----------
__global__ __launch_bounds__(256) void dual_upd(
    float* __restrict__ H, const float* __restrict__ Acc, const float* __restrict__ Den,
    const float* __restrict__ ubias,
    const float* __restrict__ Wl, const float* __restrict__ bl,
    const float* __restrict__ Wr, const float* __restrict__ br,
    float* __restrict__ Cl, float* __restrict__ Cr, int M)
{
    extern __shared__ float sh[];
    float* As  = sh;
    float* Ws0 = sh + BM * AP;
    float* Ws1 = Ws0 + 128 * WNP;
    const int tid = threadIdx.x;
    const int row0 = blockIdx.x * BM;

    stage_w128(Wl, Ws0, tid);
    stage_w128(Wr, Ws1, tid);

    for (int i = tid; i < BM * 32; i += 256) {
        int r = i >> 5, c4 = i & 31;
        int gr = row0 + r;
        float4 hv = make_float4(0.f, 0.f, 0.f, 0.f);
        if (gr < M) {
            float inv = 1.f / (Den[gr] + 1e-16f);
            float4 a = ((const float4*)Acc)[(size_t)gr * 32 + c4];
            hv = ((const float4*)H)[(size_t)gr * 32 + c4];
            const float4 bb = ((const float4*)ubias)[c4];
            hv.x += fmaxf(a.x * inv + bb.x, 0.f);
            hv.y += fmaxf(a.y * inv + bb.y, 0.f);
            hv.z += fmaxf(a.z * inv + bb.z, 0.f);
            hv.w += fmaxf(a.w * inv + bb.w, 0.f);
            ((float4*)H)[(size_t)gr * 32 + c4] = hv;
        }
        float* ap = As + r * AP + c4 * 4;
        ap[0] = tf32f(hv.x); ap[1] = tf32f(hv.y); ap[2] = tf32f(hv.z); ap[3] = tf32f(hv.w);
    }
    __syncthreads();

    const int wid = tid >> 5, lane = tid & 31;
    const int wm = wid & 3, wn = wid >> 2;
    const int gid = lane >> 2, tig = lane & 3;

    float acc[2][8][4];
#pragma unroll
    for (int ph = 0; ph < 2; ++ph) {
        const float* Ws   = ph ? Ws1 : Ws0;
        const float* bias = ph ? br  : bl;
        float* C          = ph ? Cr  : Cl;
        zero_acc(acc);
        mma_block_128(As, AP, 0, Ws, wm, wn, gid, tig, acc);
#pragma unroll
        for (int nf = 0; nf < 8; ++nf) {
            const int c = wn * 64 + nf * 8 + tig * 2;
            const float b0 = bias[c], b1 = bias[c + 1];
#pragma unroll
            for (int mf = 0; mf < 2; ++mf)
#pragma unroll
                for (int h = 0; h < 2; ++h) {
                    const int r = row0 + wm * 32 + mf * 16 + h * 8 + gid;
                    if (r < M)
                        *(float2*)(C + (size_t)r * 128 + c) =
                            make_float2(acc[mf][nf][2 * h] + b0, acc[mf][nf][2 * h + 1] + b1);
                }
        }
    }
}

// ---------- fused edge pass: 8 lanes per edge, high MLP ----------
__global__ void edge_kernel(const int* __restrict__ src, const int* __restrict__ dst,
                            const float* __restrict__ att)
{
    int idx = (int)((size_t)blockIdx.x * blockDim.x + threadIdx.x);
    int e = idx >> 3;
    if (e >= NE) return;
    int ln = idx & 7;
    int s = src[e], d = dst[e];
    const float4* xap = (const float4*)g_xl + (size_t)s * 32;
    const float4* xbp = (const float4*)g_xr + (size_t)d * 32;
    const float4* atp = (const float4*)att;

    float4 xa[4];
    float p = 0.f;
#pragma unroll
    for (int j = 0; j < 4; ++j) {
        const int c4 = ln + 8 * j;
        xa[j] = xap[c4];
        float4 xb = xbp[c4];
        float4 at = atp[c4];
        float vx = xa[j].x + xb.x; vx = vx > 0.f ? vx : 0.2f * vx;
        float vy = xa[j].y + xb.y; vy = vy > 0.f ? vy : 0.2f * vy;
        float vz = xa[j].z + xb.z; vz = vz > 0.f ? vz : 0.2f * vz;
        float vw = xa[j].w + xb.w; vw = vw > 0.f ? vw : 0.2f * vw;
        p += vx * at.x + vy * at.y + vz * at.z + vw * at.w;
    }
    p += __shfl_xor_sync(0xffffffffu, p, 4);
    p += __shfl_xor_sync(0xffffffffu, p, 2);
    p += __shfl_xor_sync(0xffffffffu, p, 1);
    float ex = __expf(p);
    if (ln == 0) atomicAdd(&g_den[d], ex);
    float* accd = g_acc + (size_t)d * 128;
#pragma unroll
    for (int j = 0; j < 4; ++j) {
        const int c = (ln + 8 * j) * 4;
        atomicAdd(accd + c + 0, ex * xa[j].x);
        atomicAdd(accd + c + 1, ex * xa[j].y);
        atomicAdd(accd + c + 2, ex * xa[j].z);
        atomicAdd(accd + c + 3, ex * xa[j].w);
    }
}

// ---------- mega head with on-the-fly update2 ----------
__global__ __launch_bounds__(256) void head_kernel(
    const float* __restrict__ H, const float* __restrict__ Acc, const float* __restrict__ Den,
    const float* __restrict__ ubias,
    const int* __restrict__ child, const int* __restrict__ parent,
    const float* __restrict__ ttab, const int* __restrict__ timei,
    const float* __restrict__ W_comb, const float* __restrict__ b_comb,
    const float* __restrict__ W_a1, const float* __restrict__ cadd,
    const float* __restrict__ W_a2, const float* __restrict__ b_a2,
    float* __restrict__ out, int M)
{
    constexpr int KP = 260;
    extern __shared__ float sh[];
    float* As  = sh;
    float* Ws  = sh + 128 * KP;
    float* red = Ws + 128 * WNP;
    const int tid = threadIdx.x;
    const int row0 = blockIdx.x * BM;

    // stage cat(h2[child], h2[parent]|0) with h2 = h1 + relu(acc/den + ubias)
    for (int i = tid; i < BM * 64; i += 256) {
        int r = i >> 6, c4 = i & 63;
        int gr = row0 + r;
        float4 v = make_float4(0.f, 0.f, 0.f, 0.f);
        if (gr < M) {
            int cc = c4 < 32 ? c4 : c4 - 32;
            int ri = c4 < 32 ? child[gr] : parent[gr];
            if (ri >= 0) {
                float inv = 1.f / (Den[ri] + 1e-16f);
                float4 a  = ((const float4*)Acc)[(size_t)ri * 32 + cc];
                v         = ((const float4*)H)[(size_t)ri * 32 + cc];
                float4 bb = ((const float4*)ubias)[cc];
                v.x += fmaxf(a.x * inv + bb.x, 0.f);
                v.y += fmaxf(a.y * inv + bb.y, 0.f);
                v.z += fmaxf(a.z * inv + bb.z, 0.f);
                v.w += fmaxf(a.w * inv + bb.w, 0.f);
            }
        }
        float* ap = As + r * KP + c4 * 4;
        ap[0] = tf32f(v.x); ap[1] = tf32f(v.y); ap[2] = tf32f(v.z); ap[3] = tf32f(v.w);
    }

    const int wid = tid >> 5, lane = tid & 31;
    const int wm = wid & 3, wn = wid >> 2;
    const int gid = lane >> 2, tig = lane & 3;

    float acc[2][8][4];
    zero_acc(acc);

    for (int kc = 0; kc < 2; ++kc) {
        __syncthreads();
        stage_w128(W_comb + kc * 128 * 128, Ws, tid);
        __syncthreads();
        mma_block_128(As, KP, kc * 128, Ws, wm, wn, gid, tig, acc);
    }
    __syncthreads();

#pragma unroll
    for (int nf = 0; nf < 8; ++nf) {
        const int c = wn * 64 + nf * 8 + tig * 2;
        const float b0 = b_comb[c], b1 = b_comb[c + 1];
#pragma unroll
        for (int mf = 0; mf < 2; ++mf)
#pragma unroll
            for (int h = 0; h < 2; ++h) {
                const int rl = wm * 32 + mf * 16 + h * 8 + gid;
                As[rl * KP + c]     = tf32f(acc[mf][nf][2 * h]     + b0);
                As[rl * KP + c + 1] = tf32f(acc[mf][nf][2 * h + 1] + b1);
            }
    }
    for (int i = tid; i < BM * 32; i += 256) {
        int r = i >> 5, c4 = i & 31;
        int gr = row0 + r;
        float4 v = make_float4(0.f, 0.f, 0.f, 0.f);
        if (gr < M) {
            int t = timei[gr];
            v = ((const float4*)(ttab + (size_t)t * 128))[c4];
        }
        float* ap = As + r * KP + 128 + c4 * 4;
        ap[0] = tf32f(v.x); ap[1] = tf32f(v.y); ap[2] = tf32f(v.z); ap[3] = tf32f(v.w);
    }

    zero_acc(acc);
    for (int kc = 0; kc < 2; ++kc) {
        __syncthreads();
        stage_w128(W_a1 + kc * 128 * 128, Ws, tid);
        __syncthreads();
        mma_block_128(As, KP, kc * 128, Ws, wm, wn, gid, tig, acc);
    }

    float p[2][2] = {{0.f, 0.f}, {0.f, 0.f}};
#pragma unroll
    for (int nf = 0; nf < 8; ++nf) {
        const int c = wn * 64 + nf * 8 + tig * 2;
        const float ca0 = cadd[c], ca1 = cadd[c + 1];
        const float w20 = W_a2[c], w21 = W_a2[c + 1];
#pragma unroll
        for (int mf = 0; mf < 2; ++mf)
#pragma unroll
            for (int h = 0; h < 2; ++h) {
                float v0 = fmaxf(acc[mf][nf][2 * h]     + ca0, 0.f);
                float v1 = fmaxf(acc[mf][nf][2 * h + 1] + ca1, 0.f);
                p[mf][h] += v0 * w20 + v1 * w21;
            }
    }
#pragma unroll
    for (int o = 1; o <= 2; o <<= 1)
#pragma unroll
        for (int mf = 0; mf < 2; ++mf)
#pragma unroll
            for (int h = 0; h < 2; ++h)
                p[mf][h] += __shfl_xor_sync(0xffffffffu, p[mf][h], o);

    __syncthreads();
    if (tig == 0) {
#pragma unroll
        for (int mf = 0; mf < 2; ++mf)
#pragma unroll
            for (int h = 0; h < 2; ++h)
                red[wn * 128 + wm * 32 + mf * 16 + h * 8 + gid] = p[mf][h];
    }
    __syncthreads();
    if (tid < 128) {
        int gr = row0 + tid;
        if (gr < M) out[gr] = red[tid] + red[128 + tid] + b_a2[0];
    }
}

// ---------------- fused context precompute ----------------
__global__ void ctx_cadd_kernel(const float* __restrict__ focal, const float* __restrict__ W_seq,
                                const float* __restrict__ b_seq,
                                const float* __restrict__ W_a1, const float* __restrict__ b_a1)
{
    __shared__ float cs[128];
    int j = threadIdx.x;
    float s = b_seq[j];
    for (int d = 0; d < DD; ++d) s += focal[d] * W_seq[d * 128 + j];
    cs[j] = s;
    __syncthreads();
    float t = b_a1[j];
    for (int k = 0; k < 128; ++k) t += cs[k] * W_a1[(256 + k) * 128 + j];
    g_cadd[j] = t;
}

// ---------------- launch ----------------
extern "C" void kernel_launch(void* const* d_in, const int* in_sizes, int n_in,
                              void* d_out, int out_size)
{
    const float* x       = (const float*)d_in[0];
    const int*   ei      = (const int*)  d_in[1];
    const float* focal   = (const float*)d_in[2];
    const int*   child   = (const int*)  d_in[3];
    const int*   parent  = (const int*)  d_in[4];
    const int*   timei   = (const int*)  d_in[5];
    const float* W_embed = (const float*)d_in[6];
    const float* b_embed = (const float*)d_in[7];
    const float* bu_Wl   = (const float*)d_in[8];
    const float* bu_bl   = (const float*)d_in[9];
    const float* bu_Wr   = (const float*)d_in[10];
    const float* bu_br   = (const float*)d_in[11];
    const float* bu_att  = (const float*)d_in[12];
    const float* bu_bias = (const float*)d_in[13];
    const float* td_Wl   = (const float*)d_in[14];
    const float* td_bl   = (const float*)d_in[15];
    const float* td_Wr   = (const float*)d_in[16];
    const float* td_br   = (const float*)d_in[17];
    const float* td_att  = (const float*)d_in[18];
    const float* td_bias = (const float*)d_in[19];
    const float* ttab    = (const float*)d_in[20];
    const float* W_comb  = (const float*)d_in[21];
    const float* b_comb  = (const float*)d_in[22];
    const float* W_a1    = (const float*)d_in[23];
    const float* b_a1    = (const float*)d_in[24];
    const float* W_a2    = (const float*)d_in[25];
    const float* b_a2    = (const float*)d_in[26];
    const float* W_seq   = (const float*)d_in[27];
    const float* b_seq   = (const float*)d_in[28];
    float* out = (float*)d_out;

    const int SM_DUAL = (BM * AP + 2 * 128 * WNP) * 4;         // ~206.8 KB
    const int SM_HEAD = (BM * 260 + 128 * WNP + 256) * 4;      // ~203.8 KB
    cudaFuncSetAttribute(embed_dual,  cudaFuncAttributeMaxDynamicSharedMemorySize, SM_DUAL);
    cudaFuncSetAttribute(dual_upd,    cudaFuncAttributeMaxDynamicSharedMemorySize, SM_DUAL);
    cudaFuncSetAttribute(head_kernel, cudaFuncAttributeMaxDynamicSharedMemorySize, SM_HEAD);

    float *hp, *xlp, *xrp, *accp, *denp, *caddp;
    cudaGetSymbolAddress((void**)&hp,    g_h);
    cudaGetSymbolAddress((void**)&xlp,   g_xl);
    cudaGetSymbolAddress((void**)&xrp,   g_xr);
    cudaGetSymbolAddress((void**)&accp,  g_acc);
    cudaGetSymbolAddress((void**)&denp,  g_den);
    cudaGetSymbolAddress((void**)&caddp, g_cadd);

    const int GEMM_BLKS_N = (NN + BM - 1) / BM;
    const int GEMM_BLKS_A = (NA + BM - 1) / BM;
    const int EDGE_BLKS   = (int)(((size_t)NE * 8 + 255) / 256);

    // 1) embed + bottom-up transforms (src = row1, dst = row0)
    embed_dual<<<GEMM_BLKS_N, 256, SM_DUAL>>>(x, W_embed, b_embed,
                                              bu_Wl, bu_bl, bu_Wr, bu_br,
                                              hp, xlp, xrp, NN);
    cudaMemsetAsync(accp, 0, (size_t)NN * HH * 4);
    cudaMemsetAsync(denp, 0, (size_t)NN * 4);
    edge_kernel<<<EDGE_BLKS, 256>>>(ei + NE, ei, bu_att);

    // 2) update1 fused + top-down transforms (src = row0, dst = row1)
    dual_upd<<<GEMM_BLKS_N, 256, SM_DUAL>>>(hp, accp, denp, bu_bias,
                                            td_Wl, td_bl, td_Wr, td_br,
                                            xlp, xrp, NN);
    cudaMemsetAsync(accp, 0, (size_t)NN * HH * 4);
    cudaMemsetAsync(denp, 0, (size_t)NN * 4);
    edge_kernel<<<EDGE_BLKS, 256>>>(ei, ei + NE, td_att);

    // 3) context fold (fused)
    ctx_cadd_kernel<<<1, 128>>>(focal, W_seq, b_seq, W_a1, b_a1);

    // 4) head with on-the-fly update2
    head_kernel<<<GEMM_BLKS_A, 256, SM_HEAD>>>(hp, accp, denp, td_bias,
                                               child, parent, ttab, timei,
                                               W_comb, b_comb, W_a1, caddp,
                                               W_a2, b_a2, out, NA);
}

// round 8
// speedup vs baseline: 2.1137x; 1.4771x over previous
#include <cuda_runtime.h>
#include <math.h>
#include <stdint.h>

#define NN   300000
#define NE   299999
#define NA   150000
#define DD   64
#define HH   128

// ---------------- scratch ----------------
__device__ float g_h   [(size_t)NN * HH];
__device__ float g_xl  [(size_t)NN * HH];
__device__ float g_xr  [(size_t)NN * HH];
__device__ float g_acc [(size_t)NN * HH];
__device__ float g_den [NN];
__device__ float g_cadd[HH];

// ---------------- tf32 helpers ----------------
__device__ __forceinline__ uint32_t f2tf32(float f)
{
    uint32_t u;
    asm("cvt.rna.tf32.f32 %0, %1;" : "=r"(u) : "f"(f));
    return u;
}
__device__ __forceinline__ float tf32f(float f) { return __uint_as_float(f2tf32(f)); }

__device__ __forceinline__ void mma_tf32(float* d, const uint32_t* a, const uint32_t* b)
{
    asm volatile(
        "mma.sync.aligned.m16n8k8.row.col.f32.tf32.tf32.f32 "
        "{%0,%1,%2,%3},{%4,%5,%6,%7},{%8,%9},{%0,%1,%2,%3};"
        : "+f"(d[0]), "+f"(d[1]), "+f"(d[2]), "+f"(d[3])
        : "r"(a[0]), "r"(a[1]), "r"(a[2]), "r"(a[3]), "r"(b[0]), "r"(b[1]));
}

#define WNP 136     // W smem pitch (64-row chunk)
#define AP  132     // A pitch (K=128)
#define APH 260     // A pitch (K=256, head)

// mainloop over one 64-k chunk. Warp tile (MF*16) x (NF*8).
template <int MF, int NF>
__device__ __forceinline__ void mma_chunk64(
    const float* As, int KP, int a_off, const float* Ws,
    int wrow, int wcol, int gid, int tig, float acc[MF][NF][4])
{
#pragma unroll
    for (int ks = 0; ks < 8; ++ks) {
        const int k0 = ks * 8;
        uint32_t a[MF][4], b[NF][2];
#pragma unroll
        for (int mf = 0; mf < MF; ++mf) {
            const float* ap = As + (wrow + mf * 16 + gid) * KP + a_off + k0;
            a[mf][0] = __float_as_uint(ap[tig]);
            a[mf][1] = __float_as_uint(ap[8 * KP + tig]);
            a[mf][2] = __float_as_uint(ap[tig + 4]);
            a[mf][3] = __float_as_uint(ap[8 * KP + tig + 4]);
        }
#pragma unroll
        for (int nf = 0; nf < NF; ++nf) {
            const int c = wcol + nf * 8 + gid;
            b[nf][0] = __float_as_uint(Ws[(k0 + tig) * WNP + c]);
            b[nf][1] = __float_as_uint(Ws[(k0 + tig + 4) * WNP + c]);
        }
#pragma unroll
        for (int mf = 0; mf < MF; ++mf)
#pragma unroll
            for (int nf = 0; nf < NF; ++nf)
                mma_tf32(acc[mf][nf], a[mf], b[nf]);
    }
}

// stage one 64-row W chunk [64 x 128] -> Ws (tf32), 256-thread block
__device__ __forceinline__ void stage_w64(const float* __restrict__ W, float* Ws, int tid)
{
    for (int i = tid; i < 64 * 32; i += 256) {
        int k = i >> 5, c4 = i & 31;
        float4 v = ((const float4*)W)[i];
        float* wp = Ws + k * WNP + c4 * 4;
        wp[0] = tf32f(v.x); wp[1] = tf32f(v.y); wp[2] = tf32f(v.z); wp[3] = tf32f(v.w);
    }
}

#define ZACC(acc, MF, NF)                             \
    _Pragma("unroll") for (int mf = 0; mf < MF; ++mf) \
    _Pragma("unroll") for (int nf = 0; nf < NF; ++nf) \
    _Pragma("unroll") for (int j = 0; j < 4; ++j) acc[mf][nf][j] = 0.f;

// ---------- fused embed + dual transform (BM=128, 2 CTAs/SM) ----------
__global__ __launch_bounds__(256, 2) void embed_dual(
    const float* __restrict__ x,
    const float* __restrict__ We, const float* __restrict__ be,
    const float* __restrict__ Wl, const float* __restrict__ bl,
    const float* __restrict__ Wr, const float* __restrict__ br,
    float* __restrict__ Hout, float* __restrict__ Cl, float* __restrict__ Cr, int M)
{
    extern __shared__ float sh[];
    float* As = sh;                  // 128 x AP (phase A uses pitch 68)
    float* Ws = sh + 128 * AP;       // 64 x WNP
    const int tid = threadIdx.x;
    const int row0 = blockIdx.x * 128;

    // phase A: stage W_embed (64 rows) + x (pitch 68)
    stage_w64(We, Ws, tid);
    for (int i = tid; i < 128 * 16; i += 256) {
        int r = i >> 4, c4 = i & 15;
        int gr = row0 + r;
        float4 v = make_float4(0.f, 0.f, 0.f, 0.f);
        if (gr < M) v = ((const float4*)(x + (size_t)gr * 64))[c4];
        float* ap = As + r * 68 + c4 * 4;
        ap[0] = tf32f(v.x); ap[1] = tf32f(v.y); ap[2] = tf32f(v.z); ap[3] = tf32f(v.w);
    }
    __syncthreads();

    const int wid = tid >> 5, lane = tid & 31;
    const int wm = wid & 3, wn = wid >> 2;          // 4x2 warp grid, tile 32x64
    const int wrow = wm * 32, wcol = wn * 64;
    const int gid = lane >> 2, tig = lane & 3;

    float acc[2][8][4];
    ZACC(acc, 2, 8)
    mma_chunk64<2, 8>(As, 68, 0, Ws, wrow, wcol, gid, tig, acc);
    __syncthreads();   // phase-A reads complete before As/Ws overwrite

    // epilogue h: write gmem + restage tf32 into As (pitch AP)
#pragma unroll
    for (int nf = 0; nf < 8; ++nf) {
        const int c = wcol + nf * 8 + tig * 2;
        const float b0 = be[c], b1 = be[c + 1];
#pragma unroll
        for (int mf = 0; mf < 2; ++mf)
#pragma unroll
            for (int h = 0; h < 2; ++h) {
                const int rl = wrow + mf * 16 + h * 8 + gid;
                const float v0 = acc[mf][nf][2 * h] + b0;
                const float v1 = acc[mf][nf][2 * h + 1] + b1;
                const int gr = row0 + rl;
                if (gr < M)
                    *(float2*)(Hout + (size_t)gr * 128 + c) = make_float2(v0, v1);
                As[rl * AP + c]     = tf32f(v0);
                As[rl * AP + c + 1] = tf32f(v1);
            }
    }

#pragma unroll
    for (int ph = 0; ph < 2; ++ph) {
        const float* W    = ph ? Wr : Wl;
        const float* bias = ph ? br : bl;
        float* C          = ph ? Cr : Cl;
        ZACC(acc, 2, 8)
#pragma unroll
        for (int kc = 0; kc < 2; ++kc) {
            __syncthreads();                       // guard prior Ws reads / As writes
            stage_w64(W + kc * 64 * 128, Ws, tid);
            __syncthreads();
            mma_chunk64<2, 8>(As, AP, kc * 64, Ws, wrow, wcol, gid, tig, acc);
        }
#pragma unroll
        for (int nf = 0; nf < 8; ++nf) {
            const int c = wcol + nf * 8 + tig * 2;
            const float b0 = bias[c], b1 = bias[c + 1];
#pragma unroll
            for (int mf = 0; mf < 2; ++mf)
#pragma unroll
                for (int h = 0; h < 2; ++h) {
                    const int r = row0 + wrow + mf * 16 + h * 8 + gid;
                    if (r < M)
                        *(float2*)(C + (size_t)r * 128 + c) =
                            make_float2(acc[mf][nf][2 * h] + b0, acc[mf][nf][2 * h + 1] + b1);
                }
        }
    }
}

// ---------- dual transform with fused update (BM=128, 2 CTAs/SM) ----------
__global__ __launch_bounds__(256, 2) void dual_upd(
    float* __restrict__ H, const float* __restrict__ Acc, const float* __restrict__ Den,
    const float* __restrict__ ubias,
    const float* __restrict__ Wl, const float* __restrict__ bl,
    const float* __restrict__ Wr, const float* __restrict__ br,
    float* __restrict__ Cl, float* __restrict__ Cr, int M)
{
    extern __shared__ float sh[];
    float* As = sh;                  // 128 x AP
    float* Ws = sh + 128 * AP;       // 64 x WNP
    const int tid = threadIdx.x;
    const int row0 = blockIdx.x * 128;

    // stage A with fused update: h1 = h + relu(acc/den + ubias)
    for (int i = tid; i < 128 * 32; i += 256) {
        int r = i >> 5, c4 = i & 31;
        int gr = row0 + r;
        float4 hv = make_float4(0.f, 0.f, 0.f, 0.f);
        if (gr < M) {
            float inv = 1.f / (Den[gr] + 1e-16f);
            float4 a = ((const float4*)Acc)[(size_t)gr * 32 + c4];
            hv = ((const float4*)H)[(size_t)gr * 32 + c4];
            const float4 bb = ((const float4*)ubias)[c4];
            hv.x += fmaxf(a.x * inv + bb.x, 0.f);
            hv.y += fmaxf(a.y * inv + bb.y, 0.f);
            hv.z += fmaxf(a.z * inv + bb.z, 0.f);
            hv.w += fmaxf(a.w * inv + bb.w, 0.f);
            ((float4*)H)[(size_t)gr * 32 + c4] = hv;
        }
        float* ap = As + r * AP + c4 * 4;
        ap[0] = tf32f(hv.x); ap[1] = tf32f(hv.y); ap[2] = tf32f(hv.z); ap[3] = tf32f(hv.w);
    }

    const int wid = tid >> 5, lane = tid & 31;
    const int wm = wid & 3, wn = wid >> 2;
    const int wrow = wm * 32, wcol = wn * 64;
    const int gid = lane >> 2, tig = lane & 3;

    float acc[2][8][4];
#pragma unroll
    for (int ph = 0; ph < 2; ++ph) {
        const float* W    = ph ? Wr : Wl;
        const float* bias = ph ? br : bl;
        float* C          = ph ? Cr : Cl;
        ZACC(acc, 2, 8)
#pragma unroll
        for (int kc = 0; kc < 2; ++kc) {
            __syncthreads();
            stage_w64(W + kc * 64 * 128, Ws, tid);
            __syncthreads();
            mma_chunk64<2, 8>(As, AP, kc * 64, Ws, wrow, wcol, gid, tig, acc);
        }
#pragma unroll
        for (int nf = 0; nf < 8; ++nf) {
            const int c = wcol + nf * 8 + tig * 2;
            const float b0 = bias[c], b1 = bias[c + 1];
#pragma unroll
            for (int mf = 0; mf < 2; ++mf)
#pragma unroll
                for (int h = 0; h < 2; ++h) {
                    const int r = row0 + wrow + mf * 16 + h * 8 + gid;
                    if (r < M)
                        *(float2*)(C + (size_t)r * 128 + c) =
                            make_float2(acc[mf][nf][2 * h] + b0, acc[mf][nf][2 * h + 1] + b1);
                }
        }
    }
}

// ---------- fused edge pass: warp per edge (R4 shape) ----------
__global__ void edge_kernel(const int* __restrict__ src, const int* __restrict__ dst,
                            const float* __restrict__ att)
{
    int e = (int)(((size_t)blockIdx.x * blockDim.x + threadIdx.x) >> 5);
    if (e >= NE) return;
    int ln = threadIdx.x & 31;
    int s = src[e], d = dst[e];
    float4 xa = ((const float4*)g_xl)[(size_t)s * 32 + ln];
    float4 xb = ((const float4*)g_xr)[(size_t)d * 32 + ln];
    float4 at = ((const float4*)att)[ln];
    float ex, ey, ez, ew;
    ex = xa.x + xb.x; ey = xa.y + xb.y; ez = xa.z + xb.z; ew = xa.w + xb.w;
    ex = ex > 0.f ? ex : 0.2f * ex;
    ey = ey > 0.f ? ey : 0.2f * ey;
    ez = ez > 0.f ? ez : 0.2f * ez;
    ew = ew > 0.f ? ew : 0.2f * ew;
    float p = ex * at.x + ey * at.y + ez * at.z + ew * at.w;
#pragma unroll
    for (int o = 16; o > 0; o >>= 1) p += __shfl_xor_sync(0xffffffffu, p, o);
    float e_ = __expf(p);
    if (ln == 0) atomicAdd(&g_den[d], e_);
    float* accd = g_acc + (size_t)d * 128 + ln * 4;
    atomicAdd(accd + 0, e_ * xa.x);
    atomicAdd(accd + 1, e_ * xa.y);
    atomicAdd(accd + 2, e_ * xa.z);
    atomicAdd(accd + 3, e_ * xa.w);
}

// ---------- mega head: BM=64, warp tile 32x32 grid 2x4, 2 CTAs/SM ----------
__global__ __launch_bounds__(256, 2) void head_kernel(
    const float* __restrict__ H, const float* __restrict__ Acc, const float* __restrict__ Den,
    const float* __restrict__ ubias,
    const int* __restrict__ child, const int* __restrict__ parent,
    const float* __restrict__ ttab, const int* __restrict__ timei,
    const float* __restrict__ W_comb, const float* __restrict__ b_comb,
    const float* __restrict__ W_a1, const float* __restrict__ cadd,
    const float* __restrict__ W_a2, const float* __restrict__ b_a2,
    float* __restrict__ out, int M)
{
    extern __shared__ float sh[];
    float* As  = sh;                  // 64 x APH
    float* Ws  = sh + 64 * APH;       // 64 x WNP
    float* red = Ws + 64 * WNP;       // 4 x 64
    const int tid = threadIdx.x;
    const int row0 = blockIdx.x * 64;

    // stage cat(h2[child], h2[parent]|0), h2 = h1 + relu(acc/den + ubias)
    for (int i = tid; i < 64 * 64; i += 256) {
        int r = i >> 6, c4 = i & 63;
        int gr = row0 + r;
        float4 v = make_float4(0.f, 0.f, 0.f, 0.f);
        if (gr < M) {
            int cc = c4 < 32 ? c4 : c4 - 32;
            int ri = c4 < 32 ? child[gr] : parent[gr];
            if (ri >= 0) {
                float inv = 1.f / (Den[ri] + 1e-16f);
                float4 a  = ((const float4*)Acc)[(size_t)ri * 32 + cc];
                v         = ((const float4*)H)[(size_t)ri * 32 + cc];
                float4 bb = ((const float4*)ubias)[cc];
                v.x += fmaxf(a.x * inv + bb.x, 0.f);
                v.y += fmaxf(a.y * inv + bb.y, 0.f);
                v.z += fmaxf(a.z * inv + bb.z, 0.f);
                v.w += fmaxf(a.w * inv + bb.w, 0.f);
            }
        }
        float* ap = As + r * APH + c4 * 4;
        ap[0] = tf32f(v.x); ap[1] = tf32f(v.y); ap[2] = tf32f(v.z); ap[3] = tf32f(v.w);
    }

    const int wid = tid >> 5, lane = tid & 31;
    const int wm = wid & 1, wn = wid >> 1;        // 2x4 warp grid, tile 32x32
    const int wrow = wm * 32, wcol = wn * 32;
    const int gid = lane >> 2, tig = lane & 3;

    float acc[2][4][4];
    ZACC(acc, 2, 4)

    // GEMM1: branch = cat @ W_comb  (K=256, 4 chunks)
#pragma unroll
    for (int kc = 0; kc < 4; ++kc) {
        __syncthreads();
        stage_w64(W_comb + kc * 64 * 128, Ws, tid);
        __syncthreads();
        mma_chunk64<2, 4>(As, APH, kc * 64, Ws, wrow, wcol, gid, tig, acc);
    }
    __syncthreads();   // GEMM1 As reads complete before overwrite

    // epilogue1: branch(+b_comb) -> As cols [0,128)
#pragma unroll
    for (int nf = 0; nf < 4; ++nf) {
        const int c = wcol + nf * 8 + tig * 2;
        const float b0 = b_comb[c], b1 = b_comb[c + 1];
#pragma unroll
        for (int mf = 0; mf < 2; ++mf)
#pragma unroll
            for (int h = 0; h < 2; ++h) {
                const int rl = wrow + mf * 16 + h * 8 + gid;
                As[rl * APH + c]     = tf32f(acc[mf][nf][2 * h]     + b0);
                As[rl * APH + c + 1] = tf32f(acc[mf][nf][2 * h + 1] + b1);
            }
    }
    // stage t_emb -> As cols [128,256)
    for (int i = tid; i < 64 * 32; i += 256) {
        int r = i >> 5, c4 = i & 31;
        int gr = row0 + r;
        float4 v = make_float4(0.f, 0.f, 0.f, 0.f);
        if (gr < M) {
            int t = timei[gr];
            v = ((const float4*)(ttab + (size_t)t * 128))[c4];
        }
        float* ap = As + r * APH + 128 + c4 * 4;
        ap[0] = tf32f(v.x); ap[1] = tf32f(v.y); ap[2] = tf32f(v.z); ap[3] = tf32f(v.w);
    }

    // GEMM2: hidden = relu(cat @ W_a1 + cadd)
    ZACC(acc, 2, 4)
#pragma unroll
    for (int kc = 0; kc < 4; ++kc) {
        __syncthreads();
        stage_w64(W_a1 + kc * 64 * 128, Ws, tid);
        __syncthreads();
        mma_chunk64<2, 4>(As, APH, kc * 64, Ws, wrow, wcol, gid, tig, acc);
    }

    // epilogue2: dot with W_a2
    float p[2][2] = {{0.f, 0.f}, {0.f, 0.f}};
#pragma unroll
    for (int nf = 0; nf < 4; ++nf) {
        const int c = wcol + nf * 8 + tig * 2;
        const float ca0 = cadd[c], ca1 = cadd[c + 1];
        const float w20 = W_a2[c], w21 = W_a2[c + 1];
#pragma unroll
        for (int mf = 0; mf < 2; ++mf)
#pragma unroll
            for (int h = 0; h < 2; ++h) {
                float v0 = fmaxf(acc[mf][nf][2 * h]     + ca0, 0.f);
                float v1 = fmaxf(acc[mf][nf][2 * h + 1] + ca1, 0.f);
                p[mf][h] += v0 * w20 + v1 * w21;
            }
    }
#pragma unroll
    for (int o = 1; o <= 2; o <<= 1)
#pragma unroll
        for (int mf = 0; mf < 2; ++mf)
#pragma unroll
            for (int h = 0; h < 2; ++h)
                p[mf][h] += __shfl_xor_sync(0xffffffffu, p[mf][h], o);

    __syncthreads();
    if (tig == 0) {
#pragma unroll
        for (int mf = 0; mf < 2; ++mf)
#pragma unroll
            for (int h = 0; h < 2; ++h)
                red[wn * 64 + wrow + mf * 16 + h * 8 + gid] = p[mf][h];
    }
    __syncthreads();
    if (tid < 64) {
        int gr = row0 + tid;
        if (gr < M)
            out[gr] = red[tid] + red[64 + tid] + red[128 + tid] + red[192 + tid] + b_a2[0];
    }
}

// ---------------- fused context precompute ----------------
__global__ void ctx_cadd_kernel(const float* __restrict__ focal, const float* __restrict__ W_seq,
                                const float* __restrict__ b_seq,
                                const float* __restrict__ W_a1, const float* __restrict__ b_a1)
{
    __shared__ float cs[128];
    int j = threadIdx.x;
    float s = b_seq[j];
    for (int d = 0; d < DD; ++d) s += focal[d] * W_seq[d * 128 + j];
    cs[j] = s;
    __syncthreads();
    float t = b_a1[j];
    for (int k = 0; k < 128; ++k) t += cs[k] * W_a1[(256 + k) * 128 + j];
    g_cadd[j] = t;
}

// ---------------- launch ----------------
extern "C" void kernel_launch(void* const* d_in, const int* in_sizes, int n_in,
                              void* d_out, int out_size)
{
    const float* x       = (const float*)d_in[0];
    const int*   ei      = (const int*)  d_in[1];
    const float* focal   = (const float*)d_in[2];
    const int*   child   = (const int*)  d_in[3];
    const int*   parent  = (const int*)  d_in[4];
    const int*   timei   = (const int*)  d_in[5];
    const float* W_embed = (const float*)d_in[6];
    const float* b_embed = (const float*)d_in[7];
    const float* bu_Wl   = (const float*)d_in[8];
    const float* bu_bl   = (const float*)d_in[9];
    const float* bu_Wr   = (const float*)d_in[10];
    const float* bu_br   = (const float*)d_in[11];
    const float* bu_att  = (const float*)d_in[12];
    const float* bu_bias = (const float*)d_in[13];
    const float* td_Wl   = (const float*)d_in[14];
    const float* td_bl   = (const float*)d_in[15];
    const float* td_Wr   = (const float*)d_in[16];
    const float* td_br   = (const float*)d_in[17];
    const float* td_att  = (const float*)d_in[18];
    const float* td_bias = (const float*)d_in[19];
    const float* ttab    = (const float*)d_in[20];
    const float* W_comb  = (const float*)d_in[21];
    const float* b_comb  = (const float*)d_in[22];
    const float* W_a1    = (const float*)d_in[23];
    const float* b_a1    = (const float*)d_in[24];
    const float* W_a2    = (const float*)d_in[25];
    const float* b_a2    = (const float*)d_in[26];
    const float* W_seq   = (const float*)d_in[27];
    const float* b_seq   = (const float*)d_in[28];
    float* out = (float*)d_out;

    const int SM_DUAL = (128 * AP + 64 * WNP) * 4;            // 102,400 B
    const int SM_HEAD = (64 * APH + 64 * WNP + 256) * 4;      // 102,400 B
    cudaFuncSetAttribute(embed_dual,  cudaFuncAttributeMaxDynamicSharedMemorySize, SM_DUAL);
    cudaFuncSetAttribute(dual_upd,    cudaFuncAttributeMaxDynamicSharedMemorySize, SM_DUAL);
    cudaFuncSetAttribute(head_kernel, cudaFuncAttributeMaxDynamicSharedMemorySize, SM_HEAD);

    float *hp, *xlp, *xrp, *accp, *denp, *caddp;
    cudaGetSymbolAddress((void**)&hp,    g_h);
    cudaGetSymbolAddress((void**)&xlp,   g_xl);
    cudaGetSymbolAddress((void**)&xrp,   g_xr);
    cudaGetSymbolAddress((void**)&accp,  g_acc);
    cudaGetSymbolAddress((void**)&denp,  g_den);
    cudaGetSymbolAddress((void**)&caddp, g_cadd);

    const int GEMM_BLKS_N = (NN + 127) / 128;
    const int HEAD_BLKS   = (NA + 63) / 64;
    const int EDGE_BLKS   = (NE + 7) / 8;

    // 1) embed + bottom-up transforms (src = row1, dst = row0)
    embed_dual<<<GEMM_BLKS_N, 256, SM_DUAL>>>(x, W_embed, b_embed,
                                              bu_Wl, bu_bl, bu_Wr, bu_br,
                                              hp, xlp, xrp, NN);
    cudaMemsetAsync(accp, 0, (size_t)NN * HH * 4);
    cudaMemsetAsync(denp, 0, (size_t)NN * 4);
    edge_kernel<<<EDGE_BLKS, 256>>>(ei + NE, ei, bu_att);

    // 2) update1 fused + top-down transforms (src = row0, dst = row1)
    dual_upd<<<GEMM_BLKS_N, 256, SM_DUAL>>>(hp, accp, denp, bu_bias,
                                            td_Wl, td_bl, td_Wr, td_br,
                                            xlp, xrp, NN);
    cudaMemsetAsync(accp, 0, (size_t)NN * HH * 4);
    cudaMemsetAsync(denp, 0, (size_t)NN * 4);
    edge_kernel<<<EDGE_BLKS, 256>>>(ei, ei + NE, td_att);

    // 3) context fold (fused)
    ctx_cadd_kernel<<<1, 128>>>(focal, W_seq, b_seq, W_a1, b_a1);

    // 4) head with on-the-fly update2
    head_kernel<<<HEAD_BLKS, 256, SM_HEAD>>>(hp, accp, denp, td_bias,
                                             child, parent, ttab, timei,
                                             W_comb, b_comb, W_a1, caddp,
                                             W_a2, b_a2, out, NA);
}

// round 9
// speedup vs baseline: 2.1192x; 1.0026x over previous
#include <cuda_runtime.h>
#include <math.h>
#include <stdint.h>

#define NN   300000
#define NE   299999
#define NA   150000
#define DD   64
#define HH   128

// ---------------- scratch ----------------
__device__ float g_h   [(size_t)NN * HH];
__device__ float g_xl  [(size_t)NN * HH];
__device__ float g_xr  [(size_t)NN * HH];
__device__ float g_acc [(size_t)NN * HH];
__device__ float g_den [NN];
__device__ float g_cadd[HH];

// ---------------- tf32 helpers ----------------
__device__ __forceinline__ uint32_t f2tf32(float f)
{
    uint32_t u;
    asm("cvt.rna.tf32.f32 %0, %1;" : "=r"(u) : "f"(f));
    return u;
}
__device__ __forceinline__ float tf32f(float f) { return __uint_as_float(f2tf32(f)); }

__device__ __forceinline__ void mma_tf32(float* d, const uint32_t* a, const uint32_t* b)
{
    asm volatile(
        "mma.sync.aligned.m16n8k8.row.col.f32.tf32.tf32.f32 "
        "{%0,%1,%2,%3},{%4,%5,%6,%7},{%8,%9},{%0,%1,%2,%3};"
        : "+f"(d[0]), "+f"(d[1]), "+f"(d[2]), "+f"(d[3])
        : "r"(a[0]), "r"(a[1]), "r"(a[2]), "r"(a[3]), "r"(b[0]), "r"(b[1]));
}

#define WNP 136     // W smem pitch (64-row chunk)
#define AP  132     // A pitch (K=128)
#define APH 260     // A pitch (K=256, head)

// mainloop over one 64-k chunk. Warp tile (MF*16) x (NF*8).
template <int MF, int NF>
__device__ __forceinline__ void mma_chunk64(
    const float* As, int KP, int a_off, const float* Ws,
    int wrow, int wcol, int gid, int tig, float acc[MF][NF][4])
{
#pragma unroll
    for (int ks = 0; ks < 8; ++ks) {
        const int k0 = ks * 8;
        uint32_t a[MF][4], b[NF][2];
#pragma unroll
        for (int mf = 0; mf < MF; ++mf) {
            const float* ap = As + (wrow + mf * 16 + gid) * KP + a_off + k0;
            a[mf][0] = __float_as_uint(ap[tig]);
            a[mf][1] = __float_as_uint(ap[8 * KP + tig]);
            a[mf][2] = __float_as_uint(ap[tig + 4]);
            a[mf][3] = __float_as_uint(ap[8 * KP + tig + 4]);
        }
#pragma unroll
        for (int nf = 0; nf < NF; ++nf) {
            const int c = wcol + nf * 8 + gid;
            b[nf][0] = __float_as_uint(Ws[(k0 + tig) * WNP + c]);
            b[nf][1] = __float_as_uint(Ws[(k0 + tig + 4) * WNP + c]);
        }
#pragma unroll
        for (int mf = 0; mf < MF; ++mf)
#pragma unroll
            for (int nf = 0; nf < NF; ++nf)
                mma_tf32(acc[mf][nf], a[mf], b[nf]);
    }
}

// stage one 64-row W chunk [64 x 128] -> Ws (tf32), 256-thread block
__device__ __forceinline__ void stage_w64(const float* __restrict__ W, float* Ws, int tid)
{
    for (int i = tid; i < 64 * 32; i += 256) {
        int k = i >> 5, c4 = i & 31;
        float4 v = ((const float4*)W)[i];
        float* wp = Ws + k * WNP + c4 * 4;
        wp[0] = tf32f(v.x); wp[1] = tf32f(v.y); wp[2] = tf32f(v.z); wp[3] = tf32f(v.w);
    }
}

#define ZACC(acc, MF, NF)                             \
    _Pragma("unroll") for (int mf = 0; mf < MF; ++mf) \
    _Pragma("unroll") for (int nf = 0; nf < NF; ++nf) \
    _Pragma("unroll") for (int j = 0; j < 4; ++j) acc[mf][nf][j] = 0.f;

// ---------- fused embed + dual transform (BM=64, 3 CTAs/SM) ----------
__global__ __launch_bounds__(256, 3) void embed_dual(
    const float* __restrict__ x,
    const float* __restrict__ We, const float* __restrict__ be,
    const float* __restrict__ Wl, const float* __restrict__ bl,
    const float* __restrict__ Wr, const float* __restrict__ br,
    float* __restrict__ Hout, float* __restrict__ Cl, float* __restrict__ Cr, int M)
{
    extern __shared__ float sh[];
    float* As = sh;                  // 64 x AP (phase A uses pitch 68)
    float* Ws = sh + 64 * AP;        // 64 x WNP
    const int tid = threadIdx.x;
    const int row0 = blockIdx.x * 64;

    // phase A: stage W_embed (64 rows) + x (pitch 68)
    stage_w64(We, Ws, tid);
    for (int i = tid; i < 64 * 16; i += 256) {
        int r = i >> 4, c4 = i & 15;
        int gr = row0 + r;
        float4 v = make_float4(0.f, 0.f, 0.f, 0.f);
        if (gr < M) v = ((const float4*)(x + (size_t)gr * 64))[c4];
        float* ap = As + r * 68 + c4 * 4;
        ap[0] = tf32f(v.x); ap[1] = tf32f(v.y); ap[2] = tf32f(v.z); ap[3] = tf32f(v.w);
    }
    __syncthreads();

    const int wid = tid >> 5, lane = tid & 31;
    const int wm = wid & 1, wn = wid >> 1;          // 2x4 warp grid, tile 32x32
    const int wrow = wm * 32, wcol = wn * 32;
    const int gid = lane >> 2, tig = lane & 3;

    float acc[2][4][4];
    ZACC(acc, 2, 4)
    mma_chunk64<2, 4>(As, 68, 0, Ws, wrow, wcol, gid, tig, acc);
    __syncthreads();   // phase-A reads complete before As/Ws overwrite

    // epilogue h: write gmem + restage tf32 into As (pitch AP)
#pragma unroll
    for (int nf = 0; nf < 4; ++nf) {
        const int c = wcol + nf * 8 + tig * 2;
        const float b0 = be[c], b1 = be[c + 1];
#pragma unroll
        for (int mf = 0; mf < 2; ++mf)
#pragma unroll
            for (int h = 0; h < 2; ++h) {
                const int rl = wrow + mf * 16 + h * 8 + gid;
                const float v0 = acc[mf][nf][2 * h] + b0;
                const float v1 = acc[mf][nf][2 * h + 1] + b1;
                const int gr = row0 + rl;
                if (gr < M)
                    *(float2*)(Hout + (size_t)gr * 128 + c) = make_float2(v0, v1);
                As[rl * AP + c]     = tf32f(v0);
                As[rl * AP + c + 1] = tf32f(v1);
            }
    }

#pragma unroll
    for (int ph = 0; ph < 2; ++ph) {
        const float* W    = ph ? Wr : Wl;
        const float* bias = ph ? br : bl;
        float* C          = ph ? Cr : Cl;
        ZACC(acc, 2, 4)
#pragma unroll
        for (int kc = 0; kc < 2; ++kc) {
            __syncthreads();                       // guard prior Ws reads / As writes
            stage_w64(W + kc * 64 * 128, Ws, tid);
            __syncthreads();
            mma_chunk64<2, 4>(As, AP, kc * 64, Ws, wrow, wcol, gid, tig, acc);
        }
#pragma unroll
        for (int nf = 0; nf < 4; ++nf) {
            const int c = wcol + nf * 8 + tig * 2;
            const float b0 = bias[c], b1 = bias[c + 1];
#pragma unroll
            for (int mf = 0; mf < 2; ++mf)
#pragma unroll
                for (int h = 0; h < 2; ++h) {
                    const int r = row0 + wrow + mf * 16 + h * 8 + gid;
                    if (r < M)
                        *(float2*)(C + (size_t)r * 128 + c) =
                            make_float2(acc[mf][nf][2 * h] + b0, acc[mf][nf][2 * h + 1] + b1);
                }
        }
    }
}

// ---------- dual transform with fused update (BM=64, 3 CTAs/SM) ----------
__global__ __launch_bounds__(256, 3) void dual_upd(
    float* __restrict__ H, const float* __restrict__ Acc, const float* __restrict__ Den,
    const float* __restrict__ ubias,
    const float* __restrict__ Wl, const float* __restrict__ bl,
    const float* __restrict__ Wr, const float* __restrict__ br,
    float* __restrict__ Cl, float* __restrict__ Cr, int M)
{
    extern __shared__ float sh[];
    float* As = sh;                  // 64 x AP
    float* Ws = sh + 64 * AP;        // 64 x WNP
    const int tid = threadIdx.x;
    const int row0 = blockIdx.x * 64;

    // stage A with fused update: h1 = h + relu(acc/den + ubias)
    for (int i = tid; i < 64 * 32; i += 256) {
        int r = i >> 5, c4 = i & 31;
        int gr = row0 + r;
        float4 hv = make_float4(0.f, 0.f, 0.f, 0.f);
        if (gr < M) {
            float inv = 1.f / (Den[gr] + 1e-16f);
            float4 a = ((const float4*)Acc)[(size_t)gr * 32 + c4];
            hv = ((const float4*)H)[(size_t)gr * 32 + c4];
            const float4 bb = ((const float4*)ubias)[c4];
            hv.x += fmaxf(a.x * inv + bb.x, 0.f);
            hv.y += fmaxf(a.y * inv + bb.y, 0.f);
            hv.z += fmaxf(a.z * inv + bb.z, 0.f);
            hv.w += fmaxf(a.w * inv + bb.w, 0.f);
            ((float4*)H)[(size_t)gr * 32 + c4] = hv;
        }
        float* ap = As + r * AP + c4 * 4;
        ap[0] = tf32f(hv.x); ap[1] = tf32f(hv.y); ap[2] = tf32f(hv.z); ap[3] = tf32f(hv.w);
    }

    const int wid = tid >> 5, lane = tid & 31;
    const int wm = wid & 1, wn = wid >> 1;
    const int wrow = wm * 32, wcol = wn * 32;
    const int gid = lane >> 2, tig = lane & 3;

    float acc[2][4][4];
#pragma unroll
    for (int ph = 0; ph < 2; ++ph) {
        const float* W    = ph ? Wr : Wl;
        const float* bias = ph ? br : bl;
        float* C          = ph ? Cr : Cl;
        ZACC(acc, 2, 4)
#pragma unroll
        for (int kc = 0; kc < 2; ++kc) {
            __syncthreads();
            stage_w64(W + kc * 64 * 128, Ws, tid);
            __syncthreads();
            mma_chunk64<2, 4>(As, AP, kc * 64, Ws, wrow, wcol, gid, tig, acc);
        }
#pragma unroll
        for (int nf = 0; nf < 4; ++nf) {
            const int c = wcol + nf * 8 + tig * 2;
            const float b0 = bias[c], b1 = bias[c + 1];
#pragma unroll
            for (int mf = 0; mf < 2; ++mf)
#pragma unroll
                for (int h = 0; h < 2; ++h) {
                    const int r = row0 + wrow + mf * 16 + h * 8 + gid;
                    if (r < M)
                        *(float2*)(C + (size_t)r * 128 + c) =
                            make_float2(acc[mf][nf][2 * h] + b0, acc[mf][nf][2 * h + 1] + b1);
                }
        }
    }
}

// ---------- fused edge pass: warp per edge ----------
__global__ void edge_kernel(const int* __restrict__ src, const int* __restrict__ dst,
                            const float* __restrict__ att)
{
    int e = (int)(((size_t)blockIdx.x * blockDim.x + threadIdx.x) >> 5);
    if (e >= NE) return;
    int ln = threadIdx.x & 31;
    int s = src[e], d = dst[e];
    float4 xa = ((const float4*)g_xl)[(size_t)s * 32 + ln];
    float4 xb = ((const float4*)g_xr)[(size_t)d * 32 + ln];
    float4 at = ((const float4*)att)[ln];
    float ex, ey, ez, ew;
    ex = xa.x + xb.x; ey = xa.y + xb.y; ez = xa.z + xb.z; ew = xa.w + xb.w;
    ex = ex > 0.f ? ex : 0.2f * ex;
    ey = ey > 0.f ? ey : 0.2f * ey;
    ez = ez > 0.f ? ez : 0.2f * ez;
    ew = ew > 0.f ? ew : 0.2f * ew;
    float p = ex * at.x + ey * at.y + ez * at.z + ew * at.w;
#pragma unroll
    for (int o = 16; o > 0; o >>= 1) p += __shfl_xor_sync(0xffffffffu, p, o);
    float e_ = __expf(p);
    if (ln == 0) atomicAdd(&g_den[d], e_);
    float* accd = g_acc + (size_t)d * 128 + ln * 4;
    atomicAdd(accd + 0, e_ * xa.x);
    atomicAdd(accd + 1, e_ * xa.y);
    atomicAdd(accd + 2, e_ * xa.z);
    atomicAdd(accd + 3, e_ * xa.w);
}

// ---------- mega head: BM=64, warp tile 32x32 grid 2x4, 2 CTAs/SM ----------
__global__ __launch_bounds__(256, 2) void head_kernel(
    const float* __restrict__ H, const float* __restrict__ Acc, const float* __restrict__ Den,
    const float* __restrict__ ubias,
    const int* __restrict__ child, const int* __restrict__ parent,
    const float* __restrict__ ttab, const int* __restrict__ timei,
    const float* __restrict__ W_comb, const float* __restrict__ b_comb,
    const float* __restrict__ W_a1, const float* __restrict__ cadd,
    const float* __restrict__ W_a2, const float* __restrict__ b_a2,
    float* __restrict__ out, int M)
{
    extern __shared__ float sh[];
    float* As  = sh;                  // 64 x APH
    float* Ws  = sh + 64 * APH;       // 64 x WNP
    float* red = Ws + 64 * WNP;       // 4 x 64
    const int tid = threadIdx.x;
    const int row0 = blockIdx.x * 64;

    // stage cat(h2[child], h2[parent]|0), h2 = h1 + relu(acc/den + ubias)
    for (int i = tid; i < 64 * 64; i += 256) {
        int r = i >> 6, c4 = i & 63;
        int gr = row0 + r;
        float4 v = make_float4(0.f, 0.f, 0.f, 0.f);
        if (gr < M) {
            int cc = c4 < 32 ? c4 : c4 - 32;
            int ri = c4 < 32 ? child[gr] : parent[gr];
            if (ri >= 0) {
                float inv = 1.f / (Den[ri] + 1e-16f);
                float4 a  = ((const float4*)Acc)[(size_t)ri * 32 + cc];
                v         = ((const float4*)H)[(size_t)ri * 32 + cc];
                float4 bb = ((const float4*)ubias)[cc];
                v.x += fmaxf(a.x * inv + bb.x, 0.f);
                v.y += fmaxf(a.y * inv + bb.y, 0.f);
                v.z += fmaxf(a.z * inv + bb.z, 0.f);
                v.w += fmaxf(a.w * inv + bb.w, 0.f);
            }
        }
        float* ap = As + r * APH + c4 * 4;
        ap[0] = tf32f(v.x); ap[1] = tf32f(v.y); ap[2] = tf32f(v.z); ap[3] = tf32f(v.w);
    }

    const int wid = tid >> 5, lane = tid & 31;
    const int wm = wid & 1, wn = wid >> 1;        // 2x4 warp grid, tile 32x32
    const int wrow = wm * 32, wcol = wn * 32;
    const int gid = lane >> 2, tig = lane & 3;

    float acc[2][4][4];
    ZACC(acc, 2, 4)

    // GEMM1: branch = cat @ W_comb  (K=256, 4 chunks)
#pragma unroll
    for (int kc = 0; kc < 4; ++kc) {
        __syncthreads();
        stage_w64(W_comb + kc * 64 * 128, Ws, tid);
        __syncthreads();
        mma_chunk64<2, 4>(As, APH, kc * 64, Ws, wrow, wcol, gid, tig, acc);
    }
    __syncthreads();   // GEMM1 As reads complete before overwrite

    // epilogue1: branch(+b_comb) -> As cols [0,128)
#pragma unroll
    for (int nf = 0; nf < 4; ++nf) {
        const int c = wcol + nf * 8 + tig * 2;
        const float b0 = b_comb[c], b1 = b_comb[c + 1];
#pragma unroll
        for (int mf = 0; mf < 2; ++mf)
#pragma unroll
            for (int h = 0; h < 2; ++h) {
                const int rl = wrow + mf * 16 + h * 8 + gid;
                As[rl * APH + c]     = tf32f(acc[mf][nf][2 * h]     + b0);
                As[rl * APH + c + 1] = tf32f(acc[mf][nf][2 * h + 1] + b1);
            }
    }
    // stage t_emb -> As cols [128,256)
    for (int i = tid; i < 64 * 32; i += 256) {
        int r = i >> 5, c4 = i & 31;
        int gr = row0 + r;
        float4 v = make_float4(0.f, 0.f, 0.f, 0.f);
        if (gr < M) {
            int t = timei[gr];
            v = ((const float4*)(ttab + (size_t)t * 128))[c4];
        }
        float* ap = As + r * APH + 128 + c4 * 4;
        ap[0] = tf32f(v.x); ap[1] = tf32f(v.y); ap[2] = tf32f(v.z); ap[3] = tf32f(v.w);
    }

    // GEMM2: hidden = relu(cat @ W_a1 + cadd)
    ZACC(acc, 2, 4)
#pragma unroll
    for (int kc = 0; kc < 4; ++kc) {
        __syncthreads();
        stage_w64(W_a1 + kc * 64 * 128, Ws, tid);
        __syncthreads();
        mma_chunk64<2, 4>(As, APH, kc * 64, Ws, wrow, wcol, gid, tig, acc);
    }

    // epilogue2: dot with W_a2
    float p[2][2] = {{0.f, 0.f}, {0.f, 0.f}};
#pragma unroll
    for (int nf = 0; nf < 4; ++nf) {
        const int c = wcol + nf * 8 + tig * 2;
        const float ca0 = cadd[c], ca1 = cadd[c + 1];
        const float w20 = W_a2[c], w21 = W_a2[c + 1];
#pragma unroll
        for (int mf = 0; mf < 2; ++mf)
#pragma unroll
            for (int h = 0; h < 2; ++h) {
                float v0 = fmaxf(acc[mf][nf][2 * h]     + ca0, 0.f);
                float v1 = fmaxf(acc[mf][nf][2 * h + 1] + ca1, 0.f);
                p[mf][h] += v0 * w20 + v1 * w21;
            }
    }
#pragma unroll
    for (int o = 1; o <= 2; o <<= 1)
#pragma unroll
        for (int mf = 0; mf < 2; ++mf)
#pragma unroll
            for (int h = 0; h < 2; ++h)
                p[mf][h] += __shfl_xor_sync(0xffffffffu, p[mf][h], o);

    __syncthreads();
    if (tig == 0) {
#pragma unroll
        for (int mf = 0; mf < 2; ++mf)
#pragma unroll
            for (int h = 0; h < 2; ++h)
                red[wn * 64 + wrow + mf * 16 + h * 8 + gid] = p[mf][h];
    }
    __syncthreads();
    if (tid < 64) {
        int gr = row0 + tid;
        if (gr < M)
            out[gr] = red[tid] + red[64 + tid] + red[128 + tid] + red[192 + tid] + b_a2[0];
    }
}

// ---------------- fused context precompute ----------------
__global__ void ctx_cadd_kernel(const float* __restrict__ focal, const float* __restrict__ W_seq,
                                const float* __restrict__ b_seq,
                                const float* __restrict__ W_a1, const float* __restrict__ b_a1)
{
    __shared__ float cs[128];
    int j = threadIdx.x;
    float s = b_seq[j];
    for (int d = 0; d < DD; ++d) s += focal[d] * W_seq[d * 128 + j];
    cs[j] = s;
    __syncthreads();
    float t = b_a1[j];
    for (int k = 0; k < 128; ++k) t += cs[k] * W_a1[(256 + k) * 128 + j];
    g_cadd[j] = t;
}

// ---------------- launch ----------------
extern "C" void kernel_launch(void* const* d_in, const int* in_sizes, int n_in,
                              void* d_out, int out_size)
{
    const float* x       = (const float*)d_in[0];
    const int*   ei      = (const int*)  d_in[1];
    const float* focal   = (const float*)d_in[2];
    const int*   child   = (const int*)  d_in[3];
    const int*   parent  = (const int*)  d_in[4];
    const int*   timei   = (const int*)  d_in[5];
    const float* W_embed = (const float*)d_in[6];
    const float* b_embed = (const float*)d_in[7];
    const float* bu_Wl   = (const float*)d_in[8];
    const float* bu_bl   = (const float*)d_in[9];
    const float* bu_Wr   = (const float*)d_in[10];
    const float* bu_br   = (const float*)d_in[11];
    const float* bu_att  = (const float*)d_in[12];
    const float* bu_bias = (const float*)d_in[13];
    const float* td_Wl   = (const float*)d_in[14];
    const float* td_bl   = (const float*)d_in[15];
    const float* td_Wr   = (const float*)d_in[16];
    const float* td_br   = (const float*)d_in[17];
    const float* td_att  = (const float*)d_in[18];
    const float* td_bias = (const float*)d_in[19];
    const float* ttab    = (const float*)d_in[20];
    const float* W_comb  = (const float*)d_in[21];
    const float* b_comb  = (const float*)d_in[22];
    const float* W_a1    = (const float*)d_in[23];
    const float* b_a1    = (const float*)d_in[24];
    const float* W_a2    = (const float*)d_in[25];
    const float* b_a2    = (const float*)d_in[26];
    const float* W_seq   = (const float*)d_in[27];
    const float* b_seq   = (const float*)d_in[28];
    float* out = (float*)d_out;

    const int SM_DUAL = (64 * AP + 64 * WNP) * 4;             // 68,608 B  (3 CTAs/SM)
    const int SM_HEAD = (64 * APH + 64 * WNP + 256) * 4;      // 102,400 B (2 CTAs/SM)
    cudaFuncSetAttribute(embed_dual,  cudaFuncAttributeMaxDynamicSharedMemorySize, SM_DUAL);
    cudaFuncSetAttribute(dual_upd,    cudaFuncAttributeMaxDynamicSharedMemorySize, SM_DUAL);
    cudaFuncSetAttribute(head_kernel, cudaFuncAttributeMaxDynamicSharedMemorySize, SM_HEAD);

    float *hp, *xlp, *xrp, *accp, *denp, *caddp;
    cudaGetSymbolAddress((void**)&hp,    g_h);
    cudaGetSymbolAddress((void**)&xlp,   g_xl);
    cudaGetSymbolAddress((void**)&xrp,   g_xr);
    cudaGetSymbolAddress((void**)&accp,  g_acc);
    cudaGetSymbolAddress((void**)&denp,  g_den);
    cudaGetSymbolAddress((void**)&caddp, g_cadd);

    const int GEMM_BLKS_N = (NN + 63) / 64;
    const int HEAD_BLKS   = (NA + 63) / 64;
    const int EDGE_BLKS   = (NE + 7) / 8;

    // 1) embed + bottom-up transforms (src = row1, dst = row0)
    embed_dual<<<GEMM_BLKS_N, 256, SM_DUAL>>>(x, W_embed, b_embed,
                                              bu_Wl, bu_bl, bu_Wr, bu_br,
                                              hp, xlp, xrp, NN);
    cudaMemsetAsync(accp, 0, (size_t)NN * HH * 4);
    cudaMemsetAsync(denp, 0, (size_t)NN * 4);
    edge_kernel<<<EDGE_BLKS, 256>>>(ei + NE, ei, bu_att);

    // 2) update1 fused + top-down transforms (src = row0, dst = row1)
    dual_upd<<<GEMM_BLKS_N, 256, SM_DUAL>>>(hp, accp, denp, bu_bias,
                                            td_Wl, td_bl, td_Wr, td_br,
                                            xlp, xrp, NN);
    cudaMemsetAsync(accp, 0, (size_t)NN * HH * 4);
    cudaMemsetAsync(denp, 0, (size_t)NN * 4);
    edge_kernel<<<EDGE_BLKS, 256>>>(ei, ei + NE, td_att);

    // 3) context fold (fused)
    ctx_cadd_kernel<<<1, 128>>>(focal, W_seq, b_seq, W_a1, b_a1);

    // 4) head with on-the-fly update2
    head_kernel<<<HEAD_BLKS, 256, SM_HEAD>>>(hp, accp, denp, td_bias,
                                             child, parent, ttab, timei,
                                             W_comb, b_comb, W_a1, caddp,
                                             W_a2, b_a2, out, NA);
}

// round 10
// speedup vs baseline: 2.1715x; 1.0247x over previous
#include <cuda_runtime.h>
#include <math.h>
#include <stdint.h>

#define NN   300000
#define NE   299999
#define NA   150000
#define DD   64
#define HH   128

// ---------------- scratch ----------------
__device__ float g_h   [(size_t)NN * HH];
__device__ float g_xl  [(size_t)NN * HH];
__device__ float g_xr  [(size_t)NN * HH];
__device__ float g_acc [(size_t)NN * HH];
__device__ float g_den [NN];
__device__ float g_cadd[HH];

// ---------------- tf32 helpers ----------------
__device__ __forceinline__ uint32_t f2tf32(float f)
{
    uint32_t u;
    asm("cvt.rna.tf32.f32 %0, %1;" : "=r"(u) : "f"(f));
    return u;
}
__device__ __forceinline__ float tf32f(float f) { return __uint_as_float(f2tf32(f)); }

__device__ __forceinline__ void mma_tf32(float* d, const uint32_t* a, const uint32_t* b)
{
    asm volatile(
        "mma.sync.aligned.m16n8k8.row.col.f32.tf32.tf32.f32 "
        "{%0,%1,%2,%3},{%4,%5,%6,%7},{%8,%9},{%0,%1,%2,%3};"
        : "+f"(d[0]), "+f"(d[1]), "+f"(d[2]), "+f"(d[3])
        : "r"(a[0]), "r"(a[1]), "r"(a[2]), "r"(a[3]), "r"(b[0]), "r"(b[1]));
}

#define WNP 136     // W smem pitch (64-row chunk)
#define AP  132     // A pitch (K=128)
#define APH 260     // A pitch (K=256, head)

// mainloop over one 64-k chunk. Warp tile (MF*16) x (NF*8).
template <int MF, int NF>
__device__ __forceinline__ void mma_chunk64(
    const float* As, int KP, int a_off, const float* Ws,
    int wrow, int wcol, int gid, int tig, float acc[MF][NF][4])
{
#pragma unroll
    for (int ks = 0; ks < 8; ++ks) {
        const int k0 = ks * 8;
        uint32_t a[MF][4], b[NF][2];
#pragma unroll
        for (int mf = 0; mf < MF; ++mf) {
            const float* ap = As + (wrow + mf * 16 + gid) * KP + a_off + k0;
            a[mf][0] = __float_as_uint(ap[tig]);
            a[mf][1] = __float_as_uint(ap[8 * KP + tig]);
            a[mf][2] = __float_as_uint(ap[tig + 4]);
            a[mf][3] = __float_as_uint(ap[8 * KP + tig + 4]);
        }
#pragma unroll
        for (int nf = 0; nf < NF; ++nf) {
            const int c = wcol + nf * 8 + gid;
            b[nf][0] = __float_as_uint(Ws[(k0 + tig) * WNP + c]);
            b[nf][1] = __float_as_uint(Ws[(k0 + tig + 4) * WNP + c]);
        }
#pragma unroll
        for (int mf = 0; mf < MF; ++mf)
#pragma unroll
            for (int nf = 0; nf < NF; ++nf)
                mma_tf32(acc[mf][nf], a[mf], b[nf]);
    }
}

// stage one 64-row W chunk [64 x 128] -> Ws (tf32), 256-thread block
__device__ __forceinline__ void stage_w64(const float* __restrict__ W, float* Ws, int tid)
{
    for (int i = tid; i < 64 * 32; i += 256) {
        int k = i >> 5, c4 = i & 31;
        float4 v = ((const float4*)W)[i];
        float* wp = Ws + k * WNP + c4 * 4;
        wp[0] = tf32f(v.x); wp[1] = tf32f(v.y); wp[2] = tf32f(v.z); wp[3] = tf32f(v.w);
    }
}

#define ZACC(acc, MF, NF)                             \
    _Pragma("unroll") for (int mf = 0; mf < MF; ++mf) \
    _Pragma("unroll") for (int nf = 0; nf < NF; ++nf) \
    _Pragma("unroll") for (int j = 0; j < 4; ++j) acc[mf][nf][j] = 0.f;

// ---------- fused embed + dual transform (BM=64, 3 CTAs/SM) + acc/den zeroing ----------
__global__ __launch_bounds__(256, 3) void embed_dual(
    const float* __restrict__ x,
    const float* __restrict__ We, const float* __restrict__ be,
    const float* __restrict__ Wl, const float* __restrict__ bl,
    const float* __restrict__ Wr, const float* __restrict__ br,
    float* __restrict__ Hout, float* __restrict__ Cl, float* __restrict__ Cr,
    float* __restrict__ Accz, float* __restrict__ Denz, int M)
{
    extern __shared__ float sh[];
    float* As = sh;                  // 64 x AP (phase A uses pitch 68)
    float* Ws = sh + 64 * AP;        // 64 x WNP
    const int tid = threadIdx.x;
    const int row0 = blockIdx.x * 64;

    // zero this block's slice of acc and den (for the following edge pass)
    {
        const float4 z4 = make_float4(0.f, 0.f, 0.f, 0.f);
        int nrow = min(64, M - row0);
        for (int i = tid; i < nrow * 32; i += 256)
            ((float4*)Accz)[(size_t)row0 * 32 + i] = z4;
        if (tid < nrow) Denz[row0 + tid] = 0.f;
    }

    // phase A: stage W_embed (64 rows) + x (pitch 68)
    stage_w64(We, Ws, tid);
    for (int i = tid; i < 64 * 16; i += 256) {
        int r = i >> 4, c4 = i & 15;
        int gr = row0 + r;
        float4 v = make_float4(0.f, 0.f, 0.f, 0.f);
        if (gr < M) v = ((const float4*)(x + (size_t)gr * 64))[c4];
        float* ap = As + r * 68 + c4 * 4;
        ap[0] = tf32f(v.x); ap[1] = tf32f(v.y); ap[2] = tf32f(v.z); ap[3] = tf32f(v.w);
    }
    __syncthreads();

    const int wid = tid >> 5, lane = tid & 31;
    const int wm = wid & 1, wn = wid >> 1;          // 2x4 warp grid, tile 32x32
    const int wrow = wm * 32, wcol = wn * 32;
    const int gid = lane >> 2, tig = lane & 3;

    float acc[2][4][4];
    ZACC(acc, 2, 4)
    mma_chunk64<2, 4>(As, 68, 0, Ws, wrow, wcol, gid, tig, acc);
    __syncthreads();   // phase-A reads complete before As/Ws overwrite

    // epilogue h: write gmem + restage tf32 into As (pitch AP)
#pragma unroll
    for (int nf = 0; nf < 4; ++nf) {
        const int c = wcol + nf * 8 + tig * 2;
        const float b0 = be[c], b1 = be[c + 1];
#pragma unroll
        for (int mf = 0; mf < 2; ++mf)
#pragma unroll
            for (int h = 0; h < 2; ++h) {
                const int rl = wrow + mf * 16 + h * 8 + gid;
                const float v0 = acc[mf][nf][2 * h] + b0;
                const float v1 = acc[mf][nf][2 * h + 1] + b1;
                const int gr = row0 + rl;
                if (gr < M)
                    *(float2*)(Hout + (size_t)gr * 128 + c) = make_float2(v0, v1);
                As[rl * AP + c]     = tf32f(v0);
                As[rl * AP + c + 1] = tf32f(v1);
            }
    }

#pragma unroll
    for (int ph = 0; ph < 2; ++ph) {
        const float* W    = ph ? Wr : Wl;
        const float* bias = ph ? br : bl;
        float* C          = ph ? Cr : Cl;
        ZACC(acc, 2, 4)
#pragma unroll
        for (int kc = 0; kc < 2; ++kc) {
            __syncthreads();                       // guard prior Ws reads / As writes
            stage_w64(W + kc * 64 * 128, Ws, tid);
            __syncthreads();
            mma_chunk64<2, 4>(As, AP, kc * 64, Ws, wrow, wcol, gid, tig, acc);
        }
#pragma unroll
        for (int nf = 0; nf < 4; ++nf) {
            const int c = wcol + nf * 8 + tig * 2;
            const float b0 = bias[c], b1 = bias[c + 1];
#pragma unroll
            for (int mf = 0; mf < 2; ++mf)
#pragma unroll
                for (int h = 0; h < 2; ++h) {
                    const int r = row0 + wrow + mf * 16 + h * 8 + gid;
                    if (r < M)
                        *(float2*)(C + (size_t)r * 128 + c) =
                            make_float2(acc[mf][nf][2 * h] + b0, acc[mf][nf][2 * h + 1] + b1);
                }
        }
    }
}

// ---------- dual transform with fused update + zero-after-read (BM=64, 3 CTAs/SM) ----------
__global__ __launch_bounds__(256, 3) void dual_upd(
    float* __restrict__ H, float* __restrict__ Acc, float* __restrict__ Den,
    const float* __restrict__ ubias,
    const float* __restrict__ Wl, const float* __restrict__ bl,
    const float* __restrict__ Wr, const float* __restrict__ br,
    float* __restrict__ Cl, float* __restrict__ Cr, int M)
{
    extern __shared__ float sh[];
    float* As = sh;                  // 64 x AP
    float* Ws = sh + 64 * AP;        // 64 x WNP
    const int tid = threadIdx.x;
    const int row0 = blockIdx.x * 64;

    // stage A with fused update: h1 = h + relu(acc/den + ubias)
    for (int i = tid; i < 64 * 32; i += 256) {
        int r = i >> 5, c4 = i & 31;
        int gr = row0 + r;
        float4 hv = make_float4(0.f, 0.f, 0.f, 0.f);
        if (gr < M) {
            float inv = 1.f / (Den[gr] + 1e-16f);
            float4 a = ((const float4*)Acc)[(size_t)gr * 32 + c4];
            hv = ((const float4*)H)[(size_t)gr * 32 + c4];
            const float4 bb = ((const float4*)ubias)[c4];
            hv.x += fmaxf(a.x * inv + bb.x, 0.f);
            hv.y += fmaxf(a.y * inv + bb.y, 0.f);
            hv.z += fmaxf(a.z * inv + bb.z, 0.f);
            hv.w += fmaxf(a.w * inv + bb.w, 0.f);
            ((float4*)H)[(size_t)gr * 32 + c4] = hv;
        }
        float* ap = As + r * AP + c4 * 4;
        ap[0] = tf32f(hv.x); ap[1] = tf32f(hv.y); ap[2] = tf32f(hv.z); ap[3] = tf32f(hv.w);
    }
    __syncthreads();   // ALL acc/den reads for this block's rows are complete

    // zero-after-read: re-zero acc/den for the next edge pass (stores drain in background)
    {
        const float4 z4 = make_float4(0.f, 0.f, 0.f, 0.f);
        int nrow = min(64, M - row0);
        for (int i = tid; i < nrow * 32; i += 256)
            ((float4*)Acc)[(size_t)row0 * 32 + i] = z4;
        if (tid < nrow) Den[row0 + tid] = 0.f;
    }

    const int wid = tid >> 5, lane = tid & 31;
    const int wm = wid & 1, wn = wid >> 1;
    const int wrow = wm * 32, wcol = wn * 32;
    const int gid = lane >> 2, tig = lane & 3;

    float acc[2][4][4];
#pragma unroll
    for (int ph = 0; ph < 2; ++ph) {
        const float* W    = ph ? Wr : Wl;
        const float* bias = ph ? br : bl;
        float* C          = ph ? Cr : Cl;
        ZACC(acc, 2, 4)
#pragma unroll
        for (int kc = 0; kc < 2; ++kc) {
            __syncthreads();
            stage_w64(W + kc * 64 * 128, Ws, tid);
            __syncthreads();
            mma_chunk64<2, 4>(As, AP, kc * 64, Ws, wrow, wcol, gid, tig, acc);
        }
#pragma unroll
        for (int nf = 0; nf < 4; ++nf) {
            const int c = wcol + nf * 8 + tig * 2;
            const float b0 = bias[c], b1 = bias[c + 1];
#pragma unroll
            for (int mf = 0; mf < 2; ++mf)
#pragma unroll
                for (int h = 0; h < 2; ++h) {
                    const int r = row0 + wrow + mf * 16 + h * 8 + gid;
                    if (r < M)
                        *(float2*)(C + (size_t)r * 128 + c) =
                            make_float2(acc[mf][nf][2 * h] + b0, acc[mf][nf][2 * h + 1] + b1);
                }
        }
    }
}

// ---------- fused edge pass: warp per edge ----------
__global__ void edge_kernel(const int* __restrict__ src, const int* __restrict__ dst,
                            const float* __restrict__ att)
{
    int e = (int)(((size_t)blockIdx.x * blockDim.x + threadIdx.x) >> 5);
    if (e >= NE) return;
    int ln = threadIdx.x & 31;
    int s = src[e], d = dst[e];
    float4 xa = ((const float4*)g_xl)[(size_t)s * 32 + ln];
    float4 xb = ((const float4*)g_xr)[(size_t)d * 32 + ln];
    float4 at = ((const float4*)att)[ln];
    float ex, ey, ez, ew;
    ex = xa.x + xb.x; ey = xa.y + xb.y; ez = xa.z + xb.z; ew = xa.w + xb.w;
    ex = ex > 0.f ? ex : 0.2f * ex;
    ey = ey > 0.f ? ey : 0.2f * ey;
    ez = ez > 0.f ? ez : 0.2f * ez;
    ew = ew > 0.f ? ew : 0.2f * ew;
    float p = ex * at.x + ey * at.y + ez * at.z + ew * at.w;
#pragma unroll
    for (int o = 16; o > 0; o >>= 1) p += __shfl_xor_sync(0xffffffffu, p, o);
    float e_ = __expf(p);
    if (ln == 0) atomicAdd(&g_den[d], e_);
    float* accd = g_acc + (size_t)d * 128 + ln * 4;
    atomicAdd(accd + 0, e_ * xa.x);
    atomicAdd(accd + 1, e_ * xa.y);
    atomicAdd(accd + 2, e_ * xa.z);
    atomicAdd(accd + 3, e_ * xa.w);
}

// ---------- mega head: BM=64, warp tile 32x32 grid 2x4, 2 CTAs/SM ----------
__global__ __launch_bounds__(256, 2) void head_kernel(
    const float* __restrict__ H, const float* __restrict__ Acc, const float* __restrict__ Den,
    const float* __restrict__ ubias,
    const int* __restrict__ child, const int* __restrict__ parent,
    const float* __restrict__ ttab, const int* __restrict__ timei,
    const float* __restrict__ W_comb, const float* __restrict__ b_comb,
    const float* __restrict__ W_a1, const float* __restrict__ cadd,
    const float* __restrict__ W_a2, const float* __restrict__ b_a2,
    float* __restrict__ out, int M)
{
    extern __shared__ float sh[];
    float* As  = sh;                  // 64 x APH
    float* Ws  = sh + 64 * APH;       // 64 x WNP
    float* red = Ws + 64 * WNP;       // 4 x 64
    const int tid = threadIdx.x;
    const int row0 = blockIdx.x * 64;

    // stage cat(h2[child], h2[parent]|0), h2 = h1 + relu(acc/den + ubias)
    for (int i = tid; i < 64 * 64; i += 256) {
        int r = i >> 6, c4 = i & 63;
        int gr = row0 + r;
        float4 v = make_float4(0.f, 0.f, 0.f, 0.f);
        if (gr < M) {
            int cc = c4 < 32 ? c4 : c4 - 32;
            int ri = c4 < 32 ? child[gr] : parent[gr];
            if (ri >= 0) {
                float inv = 1.f / (Den[ri] + 1e-16f);
                float4 a  = ((const float4*)Acc)[(size_t)ri * 32 + cc];
                v         = ((const float4*)H)[(size_t)ri * 32 + cc];
                float4 bb = ((const float4*)ubias)[cc];
                v.x += fmaxf(a.x * inv + bb.x, 0.f);
                v.y += fmaxf(a.y * inv + bb.y, 0.f);
                v.z += fmaxf(a.z * inv + bb.z, 0.f);
                v.w += fmaxf(a.w * inv + bb.w, 0.f);
            }
        }
        float* ap = As + r * APH + c4 * 4;
        ap[0] = tf32f(v.x); ap[1] = tf32f(v.y); ap[2] = tf32f(v.z); ap[3] = tf32f(v.w);
    }

    const int wid = tid >> 5, lane = tid & 31;
    const int wm = wid & 1, wn = wid >> 1;        // 2x4 warp grid, tile 32x32
    const int wrow = wm * 32, wcol = wn * 32;
    const int gid = lane >> 2, tig = lane & 3;

    float acc[2][4][4];
    ZACC(acc, 2, 4)

    // GEMM1: branch = cat @ W_comb  (K=256, 4 chunks)
#pragma unroll
    for (int kc = 0; kc < 4; ++kc) {
        __syncthreads();
        stage_w64(W_comb + kc * 64 * 128, Ws, tid);
        __syncthreads();
        mma_chunk64<2, 4>(As, APH, kc * 64, Ws, wrow, wcol, gid, tig, acc);
    }
    __syncthreads();   // GEMM1 As reads complete before overwrite

    // epilogue1: branch(+b_comb) -> As cols [0,128)
#pragma unroll
    for (int nf = 0; nf < 4; ++nf) {
        const int c = wcol + nf * 8 + tig * 2;
        const float b0 = b_comb[c], b1 = b_comb[c + 1];
#pragma unroll
        for (int mf = 0; mf < 2; ++mf)
#pragma unroll
            for (int h = 0; h < 2; ++h) {
                const int rl = wrow + mf * 16 + h * 8 + gid;
                As[rl * APH + c]     = tf32f(acc[mf][nf][2 * h]     + b0);
                As[rl * APH + c + 1] = tf32f(acc[mf][nf][2 * h + 1] + b1);
            }
    }
    // stage t_emb -> As cols [128,256)
    for (int i = tid; i < 64 * 32; i += 256) {
        int r = i >> 5, c4 = i & 31;
        int gr = row0 + r;
        float4 v = make_float4(0.f, 0.f, 0.f, 0.f);
        if (gr < M) {
            int t = timei[gr];
            v = ((const float4*)(ttab + (size_t)t * 128))[c4];
        }
        float* ap = As + r * APH + 128 + c4 * 4;
        ap[0] = tf32f(v.x); ap[1] = tf32f(v.y); ap[2] = tf32f(v.z); ap[3] = tf32f(v.w);
    }

    // GEMM2: hidden = relu(cat @ W_a1 + cadd)
    ZACC(acc, 2, 4)
#pragma unroll
    for (int kc = 0; kc < 4; ++kc) {
        __syncthreads();
        stage_w64(W_a1 + kc * 64 * 128, Ws, tid);
        __syncthreads();
        mma_chunk64<2, 4>(As, APH, kc * 64, Ws, wrow, wcol, gid, tig, acc);
    }

    // epilogue2: dot with W_a2
    float p[2][2] = {{0.f, 0.f}, {0.f, 0.f}};
#pragma unroll
    for (int nf = 0; nf < 4; ++nf) {
        const int c = wcol + nf * 8 + tig * 2;
        const float ca0 = cadd[c], ca1 = cadd[c + 1];
        const float w20 = W_a2[c], w21 = W_a2[c + 1];
#pragma unroll
        for (int mf = 0; mf < 2; ++mf)
#pragma unroll
            for (int h = 0; h < 2; ++h) {
                float v0 = fmaxf(acc[mf][nf][2 * h]     + ca0, 0.f);
                float v1 = fmaxf(acc[mf][nf][2 * h + 1] + ca1, 0.f);
                p[mf][h] += v0 * w20 + v1 * w21;
            }
    }
#pragma unroll
    for (int o = 1; o <= 2; o <<= 1)
#pragma unroll
        for (int mf = 0; mf < 2; ++mf)
#pragma unroll
            for (int h = 0; h < 2; ++h)
                p[mf][h] += __shfl_xor_sync(0xffffffffu, p[mf][h], o);

    __syncthreads();
    if (tig == 0) {
#pragma unroll
        for (int mf = 0; mf < 2; ++mf)
#pragma unroll
            for (int h = 0; h < 2; ++h)
                red[wn * 64 + wrow + mf * 16 + h * 8 + gid] = p[mf][h];
    }
    __syncthreads();
    if (tid < 64) {
        int gr = row0 + tid;
        if (gr < M)
            out[gr] = red[tid] + red[64 + tid] + red[128 + tid] + red[192 + tid] + b_a2[0];
    }
}

// ---------------- fused context precompute ----------------
__global__ void ctx_cadd_kernel(const float* __restrict__ focal, const float* __restrict__ W_seq,
                                const float* __restrict__ b_seq,
                                const float* __restrict__ W_a1, const float* __restrict__ b_a1)
{
    __shared__ float cs[128];
    int j = threadIdx.x;
    float s = b_seq[j];
    for (int d = 0; d < DD; ++d) s += focal[d] * W_seq[d * 128 + j];
    cs[j] = s;
    __syncthreads();
    float t = b_a1[j];
    for (int k = 0; k < 128; ++k) t += cs[k] * W_a1[(256 + k) * 128 + j];
    g_cadd[j] = t;
}

// ---------------- launch ----------------
extern "C" void kernel_launch(void* const* d_in, const int* in_sizes, int n_in,
                              void* d_out, int out_size)
{
    const float* x       = (const float*)d_in[0];
    const int*   ei      = (const int*)  d_in[1];
    const float* focal   = (const float*)d_in[2];
    const int*   child   = (const int*)  d_in[3];
    const int*   parent  = (const int*)  d_in[4];
    const int*   timei   = (const int*)  d_in[5];
    const float* W_embed = (const float*)d_in[6];
    const float* b_embed = (const float*)d_in[7];
    const float* bu_Wl   = (const float*)d_in[8];
    const float* bu_bl   = (const float*)d_in[9];
    const float* bu_Wr   = (const float*)d_in[10];
    const float* bu_br   = (const float*)d_in[11];
    const float* bu_att  = (const float*)d_in[12];
    const float* bu_bias = (const float*)d_in[13];
    const float* td_Wl   = (const float*)d_in[14];
    const float* td_bl   = (const float*)d_in[15];
    const float* td_Wr   = (const float*)d_in[16];
    const float* td_br   = (const float*)d_in[17];
    const float* td_att  = (const float*)d_in[18];
    const float* td_bias = (const float*)d_in[19];
    const float* ttab    = (const float*)d_in[20];
    const float* W_comb  = (const float*)d_in[21];
    const float* b_comb  = (const float*)d_in[22];
    const float* W_a1    = (const float*)d_in[23];
    const float* b_a1    = (const float*)d_in[24];
    const float* W_a2    = (const float*)d_in[25];
    const float* b_a2    = (const float*)d_in[26];
    const float* W_seq   = (const float*)d_in[27];
    const float* b_seq   = (const float*)d_in[28];
    float* out = (float*)d_out;

    const int SM_DUAL = (64 * AP + 64 * WNP) * 4;             // 68,608 B  (3 CTAs/SM)
    const int SM_HEAD = (64 * APH + 64 * WNP + 256) * 4;      // 102,400 B (2 CTAs/SM)
    cudaFuncSetAttribute(embed_dual,  cudaFuncAttributeMaxDynamicSharedMemorySize, SM_DUAL);
    cudaFuncSetAttribute(dual_upd,    cudaFuncAttributeMaxDynamicSharedMemorySize, SM_DUAL);
    cudaFuncSetAttribute(head_kernel, cudaFuncAttributeMaxDynamicSharedMemorySize, SM_HEAD);

    float *hp, *xlp, *xrp, *accp, *denp, *caddp;
    cudaGetSymbolAddress((void**)&hp,    g_h);
    cudaGetSymbolAddress((void**)&xlp,   g_xl);
    cudaGetSymbolAddress((void**)&xrp,   g_xr);
    cudaGetSymbolAddress((void**)&accp,  g_acc);
    cudaGetSymbolAddress((void**)&denp,  g_den);
    cudaGetSymbolAddress((void**)&caddp, g_cadd);

    const int GEMM_BLKS_N = (NN + 63) / 64;
    const int HEAD_BLKS   = (NA + 63) / 64;
    const int EDGE_BLKS   = (NE + 7) / 8;

    // 0) context fold (tiny, no deps on pipeline)
    ctx_cadd_kernel<<<1, 128>>>(focal, W_seq, b_seq, W_a1, b_a1);

    // 1) embed + bottom-up transforms + acc/den zeroing (src = row1, dst = row0)
    embed_dual<<<GEMM_BLKS_N, 256, SM_DUAL>>>(x, W_embed, b_embed,
                                              bu_Wl, bu_bl, bu_Wr, bu_br,
                                              hp, xlp, xrp, accp, denp, NN);
    edge_kernel<<<EDGE_BLKS, 256>>>(ei + NE, ei, bu_att);

    // 2) update1 fused + top-down transforms + zero-after-read (src = row0, dst = row1)
    dual_upd<<<GEMM_BLKS_N, 256, SM_DUAL>>>(hp, accp, denp, bu_bias,
                                            td_Wl, td_bl, td_Wr, td_br,
                                            xlp, xrp, NN);
    edge_kernel<<<EDGE_BLKS, 256>>>(ei, ei + NE, td_att);

    // 3) head with on-the-fly update2
    head_kernel<<<HEAD_BLKS, 256, SM_HEAD>>>(hp, accp, denp, td_bias,
                                             child, parent, ttab, timei,
                                             W_comb, b_comb, W_a1, caddp,
                                             W_a2, b_a2, out, NA);
}